// round 13
// baseline (speedup 1.0000x reference)
#include <cuda_runtime.h>
#include <cuda_bf16.h>
#include <cstdint>
#include <cstddef>

#define BB 4
#define HH 160
#define WW 160
#define HWSZ (HH*WW)
#define CPAD 40          // padded channel stride (u16) for conv staging
#define FPAD 72          // padded k stride (u16) for fc phase

typedef unsigned long long ull;

// ---------------- packed f32x2 helpers (fp32 kernels) ----------------------
__device__ __forceinline__ ull pk2(float lo, float hi) {
    ull r; asm("mov.b64 %0,{%1,%2};" : "=l"(r) : "f"(lo), "f"(hi)); return r;
}
__device__ __forceinline__ void upk2(ull v, float& lo, float& hi) {
    asm("mov.b64 {%0,%1},%2;" : "=f"(lo), "=f"(hi) : "l"(v));
}
__device__ __forceinline__ ull f2fma(ull a, ull b, ull c) {
    ull d; asm("fma.rn.f32x2 %0,%1,%2,%3;" : "=l"(d) : "l"(a), "l"(b), "l"(c)); return d;
}

// ---------------- bf16 mma.sync helpers ------------------------------------
__device__ __forceinline__ void mma_bf16(float d[4], const uint32_t a[4],
                                         uint32_t b0, uint32_t b1) {
    asm volatile(
        "mma.sync.aligned.m16n8k16.row.col.f32.bf16.bf16.f32 "
        "{%0,%1,%2,%3}, {%4,%5,%6,%7}, {%8,%9}, {%0,%1,%2,%3};"
        : "+f"(d[0]), "+f"(d[1]), "+f"(d[2]), "+f"(d[3])
        : "r"(a[0]), "r"(a[1]), "r"(a[2]), "r"(a[3]), "r"(b0), "r"(b1));
}
__device__ __forceinline__ uint32_t bfpack2(float x, float y) {
    __nv_bfloat162 h = __halves2bfloat162(__float2bfloat16(x), __float2bfloat16(y));
    return *(uint32_t*)&h;
}
__device__ __forceinline__ float bfunp_lo(uint32_t v) {
    __nv_bfloat162 h = *(__nv_bfloat162*)&v;
    return __bfloat162float(__low2bfloat16(h));
}
__device__ __forceinline__ float bfunp_hi(uint32_t v) {
    __nv_bfloat162 h = *(__nv_bfloat162*)&v;
    return __bfloat162float(__high2bfloat16(h));
}

// ---------------- scratch (device globals; no allocation allowed) ----------
__device__ __align__(128) float g_gmap[BB*HWSZ];
__device__ __align__(128) float g_smap[BB*HWSZ];
__device__ __align__(128) float g_fusion[BB*64*HWSZ];
__device__ __align__(128) float g_Weff[64*64];
__device__ __align__(128) float g_beff[64];
__device__ __align__(128) float g_b2[64];         // BN-folded bias
__device__ __align__(128) uint4 g_wf[9216];       // conv64 frags [t][kh][ks][nt8][lane]
__device__ __align__(128) uint4 g_fcf[1024];      // fc frags [ks][nt8][lane]
__device__ __align__(128) uint4 g_wf1[4608];      // conv32 frags [t][kh][ks][nt4][lane]

// ---------------- K0a: effective dyn1d weights (sum over K) ----------------
__global__ void build_weff(const float* __restrict__ rk5w, const float* __restrict__ rk5b,
                           const float* __restrict__ rk7w, const float* __restrict__ rk7b,
                           const float* __restrict__ lk5w, const float* __restrict__ lk5b,
                           const float* __restrict__ lk7w, const float* __restrict__ lk7b)
{
    int id = blockIdx.x*blockDim.x + threadIdx.x;
    if (id >= 64*64) return;
    int m = id >> 6, c = id & 63;
    const float* w; const float* bs; int K, o;
    if      (m < 16) { w = rk5w; bs = rk5b; K = 5; o = m;    }
    else if (m < 32) { w = rk7w; bs = rk7b; K = 7; o = m-16; }
    else if (m < 48) { w = lk5w; bs = lk5b; K = 5; o = m-32; }
    else             { w = lk7w; bs = lk7b; K = 7; o = m-48; }
    float acc = 0.f;
    for (int k = 0; k < K; k++) acc += w[(o*K + k)*64 + c];
    g_Weff[m*64 + c] = acc;
    if (c == 0) {
        float bacc = 0.f;
        for (int k = 0; k < K; k++) bacc += bs[o*K + k];
        g_beff[m] = bacc;
    }
}

// ---------------- K0b: BN-folded bias for conv64 ---------------------------
__global__ void prep_b(const float* __restrict__ b2s, const float* __restrict__ bg,
                       const float* __restrict__ bbta, const float* __restrict__ bm,
                       const float* __restrict__ bv)
{
    int id = blockIdx.x*blockDim.x + threadIdx.x;
    if (id < 64) {
        float scc = bg[id] * rsqrtf(bv[id] + 1e-5f);
        g_b2[id] = b2s[id]*scc + bbta[id] - bm[id]*scc;
    }
}

// ---------------- K0c: pack mma B-fragments (hi/lo split) ------------------
__global__ void prep_frag(const float* __restrict__ sfw, const float* __restrict__ bg,
                          const float* __restrict__ bv, const float* __restrict__ fcw,
                          const float* __restrict__ w1)
{
    int id = blockIdx.x*blockDim.x + threadIdx.x;
    if (id < 9216) {
        int lane = id & 31; int rem = id >> 5;
        int nt = rem & 7; rem >>= 3;
        int ks = rem & 1; rem >>= 1;
        int kh = rem & 1; int t = rem >> 1;
        int n  = nt*8 + (lane >> 2);
        int k0 = kh*32 + ks*16 + (lane & 3)*2;
        float sc = bg[n] * rsqrtf(bv[n] + 1e-5f);
        float w00 = sfw[(n*64 + k0    )*9 + t] * sc;
        float w01 = sfw[(n*64 + k0 + 1)*9 + t] * sc;
        float w08 = sfw[(n*64 + k0 + 8)*9 + t] * sc;
        float w09 = sfw[(n*64 + k0 + 9)*9 + t] * sc;
        __nv_bfloat16 h00 = __float2bfloat16(w00), h01 = __float2bfloat16(w01);
        __nv_bfloat16 h08 = __float2bfloat16(w08), h09 = __float2bfloat16(w09);
        uint4 rec;
        rec.x = (uint32_t)(*(uint16_t*)&h00) | ((uint32_t)(*(uint16_t*)&h01) << 16);
        rec.y = (uint32_t)(*(uint16_t*)&h08) | ((uint32_t)(*(uint16_t*)&h09) << 16);
        rec.z = bfpack2(w00 - __bfloat162float(h00), w01 - __bfloat162float(h01));
        rec.w = bfpack2(w08 - __bfloat162float(h08), w09 - __bfloat162float(h09));
        g_wf[id] = rec;
    } else if (id < 10240) {
        int fid = id - 9216;
        int lane = fid & 31; int rem = fid >> 5;
        int nt = rem & 7; int ks = rem >> 3;
        int n  = nt*8 + (lane >> 2);
        int k0 = ks*16 + (lane & 3)*2;
        float w00 = fcw[n*64 + k0    ];
        float w01 = fcw[n*64 + k0 + 1];
        float w08 = fcw[n*64 + k0 + 8];
        float w09 = fcw[n*64 + k0 + 9];
        __nv_bfloat16 h00 = __float2bfloat16(w00), h01 = __float2bfloat16(w01);
        __nv_bfloat16 h08 = __float2bfloat16(w08), h09 = __float2bfloat16(w09);
        uint4 rec;
        rec.x = (uint32_t)(*(uint16_t*)&h00) | ((uint32_t)(*(uint16_t*)&h01) << 16);
        rec.y = (uint32_t)(*(uint16_t*)&h08) | ((uint32_t)(*(uint16_t*)&h09) << 16);
        rec.z = bfpack2(w00 - __bfloat162float(h00), w01 - __bfloat162float(h01));
        rec.w = bfpack2(w08 - __bfloat162float(h08), w09 - __bfloat162float(h09));
        g_fcf[fid] = rec;
    } else if (id < 14848) {
        int fid = id - 10240;
        int lane = fid & 31; int rem = fid >> 5;
        int nt = rem & 3; rem >>= 2;
        int ks = rem & 1; rem >>= 1;
        int kh = rem & 1; int t = rem >> 1;
        int n  = nt*8 + (lane >> 2);          // oc 0..31
        int k0 = kh*32 + ks*16 + (lane & 3)*2;
        float w00 = w1[(n*64 + k0    )*9 + t];
        float w01 = w1[(n*64 + k0 + 1)*9 + t];
        float w08 = w1[(n*64 + k0 + 8)*9 + t];
        float w09 = w1[(n*64 + k0 + 9)*9 + t];
        __nv_bfloat16 h00 = __float2bfloat16(w00), h01 = __float2bfloat16(w01);
        __nv_bfloat16 h08 = __float2bfloat16(w08), h09 = __float2bfloat16(w09);
        uint4 rec;
        rec.x = (uint32_t)(*(uint16_t*)&h00) | ((uint32_t)(*(uint16_t*)&h01) << 16);
        rec.y = (uint32_t)(*(uint16_t*)&h08) | ((uint32_t)(*(uint16_t*)&h09) << 16);
        rec.z = bfpack2(w00 - __bfloat162float(h00), w01 - __bfloat162float(h01));
        rec.w = bfpack2(w08 - __bfloat162float(h08), w09 - __bfloat162float(h09));
        g_wf1[fid] = rec;
    }
}

// ---------------- K1: conv3x3<32> + sobel edge + attention via mma.sync ----
// Block = 32w x 4h (M=128 px), N=32 oc, 256 thr = 8 warps.
// Edge/sumx computed FROM the MMA A-fragments (zero extra LDS): the tap loop
// already materializes the full 3x3 neighborhood per channel. Channels are
// disjoint across quad lanes -> abs-then-quad-shfl reduce is exact.
__global__ __launch_bounds__(256)
void conv32_edge_mma(const float* __restrict__ x,
                     const uint4* __restrict__ wf1, const float* __restrict__ b1,
                     const float* __restrict__ baw2, const float* __restrict__ bab2)
{
    __shared__ __align__(16) uint16_t s_hi[204*CPAD];   // [6*34][40]
    __shared__ __align__(16) uint16_t s_lo[204*CPAD];
    __shared__ float s_b1[32], s_w2[32];

    const int tid = threadIdx.x;
    const int wid = tid >> 5, lane = tid & 31;
    const int g = lane >> 2, t2 = (lane & 3) * 2;
    const int b  = blockIdx.z;
    const int w0 = blockIdx.x*32, h0 = blockIdx.y*4;

    if (tid < 32) { s_b1[tid] = b1[tid]; s_w2[tid] = baw2[tid]; }

    const int m0 = wid*16 + g, m1 = m0 + 8;
    const int ph0 = m0 >> 5, pw0 = m0 & 31;
    const int ph1 = m1 >> 5, pw1 = m1 & 31;

    float d[4][4];
    #pragma unroll
    for (int nt = 0; nt < 4; nt++)
        #pragma unroll
        for (int i = 0; i < 4; i++) d[nt][i] = 0.f;
    float edge0 = 0.f, edge1 = 0.f, sum0 = 0.f, sum1 = 0.f;

    // sobel coefficients by tap t = dr*3+dc, per kh (x for ch<32, y for ch>=32)
    const float SOB[2][9] = {
        {-1.f, 0.f, 1.f, -2.f, 0.f, 2.f, -1.f, 0.f, 1.f},
        {-1.f, -2.f, -1.f, 0.f, 0.f, 0.f, 1.f, 2.f, 1.f}
    };

    #pragma unroll
    for (int kh = 0; kh < 2; kh++) {
        if (kh) __syncthreads();
        #pragma unroll
        for (int it = 0; it < 13; it++) {
            int idx = tid + it*256;
            if (idx < 3264) {
                int hw = idx >> 4, cp = idx & 15;
                int h = hw / 34, w = hw % 34;
                int gh = h0 - 1 + h, gw = w0 - 1 + w;
                bool inb = (gh >= 0 && gh < HH && gw >= 0 && gw < WW);
                int ci = kh*32 + cp*2;
                const float* fp = x + ((size_t)(b*64 + ci))*HWSZ + (inb ? gh*WW + gw : 0);
                float v0 = inb ? fp[0] : 0.f;
                float v1 = inb ? fp[HWSZ] : 0.f;
                __nv_bfloat16 h0b = __float2bfloat16(v0);
                __nv_bfloat16 h1b = __float2bfloat16(v1);
                uint32_t hiw = (uint32_t)(*(uint16_t*)&h0b) | ((uint32_t)(*(uint16_t*)&h1b) << 16);
                uint32_t low = bfpack2(v0 - __bfloat162float(h0b), v1 - __bfloat162float(h1b));
                *(uint32_t*)&s_hi[hw*CPAD + cp*2] = hiw;
                *(uint32_t*)&s_lo[hw*CPAD + cp*2] = low;
            }
        }
        __syncthreads();

        // per-channel sobel accumulators for this kh: [ks][slot] (.x = ch k, .y = ch k+1)
        float2 gx[2][4];
        #pragma unroll
        for (int ks = 0; ks < 2; ks++)
            #pragma unroll
            for (int sl = 0; sl < 4; sl++) gx[ks][sl] = make_float2(0.f, 0.f);

        #pragma unroll
        for (int t = 0; t < 9; t++) {
            const int dr = t/3, dc = t%3;
            const float cf = SOB[kh][t];
            const int r0 = ((ph0 + dr)*34 + pw0 + dc)*CPAD;
            const int r1 = ((ph1 + dr)*34 + pw1 + dc)*CPAD;
            #pragma unroll
            for (int ks = 0; ks < 2; ks++) {
                uint2 bfr[4];
                const uint2* wp = (const uint2*)(wf1 + (size_t)(((t*2 + kh)*2 + ks)*4)*32 + lane);
                #pragma unroll
                for (int nt = 0; nt < 4; nt++) bfr[nt] = wp[nt*64];

                const int k = ks*16 + t2;
                uint32_t ah[4], al[4];
                ah[0] = *(const uint32_t*)&s_hi[r0 + k];
                ah[1] = *(const uint32_t*)&s_hi[r1 + k];
                ah[2] = *(const uint32_t*)&s_hi[r0 + k + 8];
                ah[3] = *(const uint32_t*)&s_hi[r1 + k + 8];
                al[0] = *(const uint32_t*)&s_lo[r0 + k];
                al[1] = *(const uint32_t*)&s_lo[r1 + k];
                al[2] = *(const uint32_t*)&s_lo[r0 + k + 8];
                al[3] = *(const uint32_t*)&s_lo[r1 + k + 8];

                #pragma unroll
                for (int nt = 0; nt < 4; nt++) {
                    mma_bf16(d[nt], ah, bfr[nt].x, bfr[nt].y);
                    mma_bf16(d[nt], al, bfr[nt].x, bfr[nt].y);
                }

                if (cf != 0.f) {
                    #pragma unroll
                    for (int sl = 0; sl < 4; sl++) {
                        gx[ks][sl].x += cf * bfunp_lo(ah[sl]);
                        gx[ks][sl].y += cf * bfunp_hi(ah[sl]);
                    }
                }
                if (t == 4) {   // center tap: channel-sum (hi+lo precision)
                    sum0 += bfunp_lo(ah[0]) + bfunp_hi(ah[0]) + bfunp_lo(al[0]) + bfunp_hi(al[0])
                          + bfunp_lo(ah[2]) + bfunp_hi(ah[2]) + bfunp_lo(al[2]) + bfunp_hi(al[2]);
                    sum1 += bfunp_lo(ah[1]) + bfunp_hi(ah[1]) + bfunp_lo(al[1]) + bfunp_hi(al[1])
                          + bfunp_lo(ah[3]) + bfunp_hi(ah[3]) + bfunp_lo(al[3]) + bfunp_hi(al[3]);
                }
            }
        }

        #pragma unroll
        for (int ks = 0; ks < 2; ks++) {
            edge0 += fabsf(gx[ks][0].x) + fabsf(gx[ks][0].y)
                   + fabsf(gx[ks][2].x) + fabsf(gx[ks][2].y);
            edge1 += fabsf(gx[ks][1].x) + fabsf(gx[ks][1].y)
                   + fabsf(gx[ks][3].x) + fabsf(gx[ks][3].y);
        }
    }

    // attention partial from D fragments
    float att0 = 0.f, att1 = 0.f;
    #pragma unroll
    for (int nt = 0; nt < 4; nt++) {
        int oc = nt*8 + t2;
        float b0v = s_b1[oc], b1v = s_b1[oc+1];
        float w0v = s_w2[oc], w1v = s_w2[oc+1];
        att0 += w0v*fmaxf(d[nt][0] + b0v, 0.f) + w1v*fmaxf(d[nt][1] + b1v, 0.f);
        att1 += w0v*fmaxf(d[nt][2] + b0v, 0.f) + w1v*fmaxf(d[nt][3] + b1v, 0.f);
    }
    // quad reduction (channels are disjoint across the 4 lanes)
    #pragma unroll
    for (int msk = 1; msk <= 2; msk <<= 1) {
        att0  += __shfl_xor_sync(0xFFFFFFFF, att0,  msk);
        att1  += __shfl_xor_sync(0xFFFFFFFF, att1,  msk);
        edge0 += __shfl_xor_sync(0xFFFFFFFF, edge0, msk);
        edge1 += __shfl_xor_sync(0xFFFFFFFF, edge1, msk);
        sum0  += __shfl_xor_sync(0xFFFFFFFF, sum0,  msk);
        sum1  += __shfl_xor_sync(0xFFFFFFFF, sum1,  msk);
    }

    if ((lane & 3) == 0) {
        float bb = bab2[0];
        #pragma unroll
        for (int r = 0; r < 2; r++) {
            int m = r ? m1 : m0;
            float att = (r ? att1 : att0) + bb;
            float ed = (r ? edge1 : edge0) * (1.f/32.f);
            float sx = (r ? sum1 : sum0);
            float z = att + ed;
            float a = 1.f / (1.f + expf(-z));
            float gv = 1.f + a;
            int mh = m >> 5, mw = m & 31;
            size_t pix = (size_t)b*HWSZ + (size_t)(h0 + mh)*WW + (w0 + mw);
            g_gmap[pix] = gv;
            g_smap[pix] = gv * sx;
        }
    }
}

// ---------------- K3: fusion GEMM, m-split, prefetched loads (unchanged) ---
__global__ __launch_bounds__(256)
void fusion_k(const float* __restrict__ in, const float* __restrict__ wsrc,
              const float* __restrict__ bsrc, float* __restrict__ outp)
{
    __shared__ __align__(16) float s_w[64][32];
    __shared__ float s_b[32];
    const int tid = threadIdx.x;
    const int ms  = blockIdx.y;
    const int b   = blockIdx.z;
    for (int i = tid; i < 2048; i += 256) {
        int ci = i >> 5, m = i & 31;
        s_w[ci][m] = wsrc[(ms*32 + m)*64 + ci];
    }
    if (tid < 32) s_b[tid] = bsrc[ms*32 + tid];
    __syncthreads();

    const int mg    = tid >> 6;
    const int mbase = mg*8;
    const int slot  = tid & 63;
    const int pix   = blockIdx.x*256 + slot*4;
    const float* basep = in + (size_t)b*64*HWSZ + pix;

    ull acc[4][4];
    #pragma unroll
    for (int m = 0; m < 4; m++)
        #pragma unroll
        for (int p = 0; p < 4; p++) acc[m][p] = 0ULL;

    float4 xv[4];
    #pragma unroll
    for (int j = 0; j < 4; j++)
        xv[j] = *(const float4*)(basep + (size_t)j*HWSZ);

    #pragma unroll 1
    for (int c4 = 0; c4 < 16; c4++) {
        float4 xn[4];
        if (c4 < 15) {
            const float* bp = basep + (size_t)(c4+1)*4*HWSZ;
            #pragma unroll
            for (int j = 0; j < 4; j++)
                xn[j] = *(const float4*)(bp + (size_t)j*HWSZ);
        }
        #pragma unroll
        for (int j = 0; j < 4; j++) {
            ull xd0 = pk2(xv[j].x, xv[j].x);
            ull xd1 = pk2(xv[j].y, xv[j].y);
            ull xd2 = pk2(xv[j].z, xv[j].z);
            ull xd3 = pk2(xv[j].w, xv[j].w);
            const ulonglong2* wp = (const ulonglong2*)&s_w[c4*4 + j][mbase];
            ulonglong2 wA = wp[0], wB = wp[1];
            acc[0][0]=f2fma(wA.x,xd0,acc[0][0]); acc[0][1]=f2fma(wA.x,xd1,acc[0][1]);
            acc[0][2]=f2fma(wA.x,xd2,acc[0][2]); acc[0][3]=f2fma(wA.x,xd3,acc[0][3]);
            acc[1][0]=f2fma(wA.y,xd0,acc[1][0]); acc[1][1]=f2fma(wA.y,xd1,acc[1][1]);
            acc[1][2]=f2fma(wA.y,xd2,acc[1][2]); acc[1][3]=f2fma(wA.y,xd3,acc[1][3]);
            acc[2][0]=f2fma(wB.x,xd0,acc[2][0]); acc[2][1]=f2fma(wB.x,xd1,acc[2][1]);
            acc[2][2]=f2fma(wB.x,xd2,acc[2][2]); acc[2][3]=f2fma(wB.x,xd3,acc[2][3]);
            acc[3][0]=f2fma(wB.y,xd0,acc[3][0]); acc[3][1]=f2fma(wB.y,xd1,acc[3][1]);
            acc[3][2]=f2fma(wB.y,xd2,acc[3][2]); acc[3][3]=f2fma(wB.y,xd3,acc[3][3]);
        }
        if (c4 < 15) {
            #pragma unroll
            for (int j = 0; j < 4; j++) xv[j] = xn[j];
        }
    }

    float4 gv = *(const float4*)&g_gmap[(size_t)b*HWSZ + pix];
    float4 sv = *(const float4*)&g_smap[(size_t)b*HWSZ + pix];
    float gs[4] = {gv.x, gv.y, gv.z, gv.w};
    float ss[4] = {sv.x, sv.y, sv.z, sv.w};
    #pragma unroll
    for (int mp = 0; mp < 4; mp++) {
        int ch = ms*32 + mbase + 2*mp;
        float b0 = s_b[mbase + 2*mp], b1 = s_b[mbase + 2*mp + 1];
        float lo[4], hi[4];
        #pragma unroll
        for (int p = 0; p < 4; p++) {
            float alo, ahi;
            upk2(acc[mp][p], alo, ahi);
            lo[p] = ss[p] * (gs[p]*alo + b0);
            hi[p] = ss[p] * (gs[p]*ahi + b1);
        }
        float4 vlo = {lo[0], lo[1], lo[2], lo[3]};
        float4 vhi = {hi[0], hi[1], hi[2], hi[3]};
        *(float4*)&outp[((size_t)(b*64 + ch  ))*HWSZ + pix] = vlo;
        *(float4*)&outp[((size_t)(b*64 + ch+1))*HWSZ + pix] = vhi;
    }
}

// ---------------- K4: conv3x3<64> + fc + residual via bf16 mma.sync --------
// Padded strides: conv CPAD=40 (80B rows), fc FPAD=72 (144B rows) -> no conflicts.
__global__ __launch_bounds__(256)
void conv64fc_mma(const float* __restrict__ fus,
                  const uint4* __restrict__ wf, const float* __restrict__ b2,
                  const uint4* __restrict__ fcf, const float* __restrict__ fcb,
                  const float* __restrict__ resid, float* __restrict__ out)
{
    __shared__ __align__(16) uint16_t s_buf[2*128*FPAD];   // 36864B
    __shared__ float s_b2[64], s_fcb[64];

    const int tid = threadIdx.x;
    const int wid = tid >> 5, lane = tid & 31;
    const int g = lane >> 2, t2 = (lane & 3) * 2;
    const int b  = blockIdx.z;
    const int w0 = blockIdx.x*32, h0 = blockIdx.y*4;

    if (tid < 64) { s_b2[tid] = b2[tid]; s_fcb[tid] = fcb[tid]; }

    uint16_t* s_hi = s_buf;
    uint16_t* s_lo = s_buf + 128*FPAD;

    const int m0 = wid*16 + g, m1 = m0 + 8;
    const int ph0 = m0 >> 5, pw0 = m0 & 31;
    const int ph1 = m1 >> 5, pw1 = m1 & 31;

    float d[8][4];
    #pragma unroll
    for (int nt = 0; nt < 8; nt++)
        #pragma unroll
        for (int i = 0; i < 4; i++) d[nt][i] = 0.f;

    for (int kh = 0; kh < 2; kh++) {
        if (kh) __syncthreads();
        #pragma unroll
        for (int it = 0; it < 13; it++) {
            int idx = tid + it*256;
            if (idx < 3264) {
                int hw = idx >> 4, cp = idx & 15;
                int h = hw / 34, w = hw % 34;
                int gh = h0 - 1 + h, gw = w0 - 1 + w;
                bool inb = (gh >= 0 && gh < HH && gw >= 0 && gw < WW);
                int ci = kh*32 + cp*2;
                const float* fp = fus + ((size_t)(b*64 + ci))*HWSZ + (inb ? gh*WW + gw : 0);
                float v0 = inb ? fp[0] : 0.f;
                float v1 = inb ? fp[HWSZ] : 0.f;
                __nv_bfloat16 h0b = __float2bfloat16(v0);
                __nv_bfloat16 h1b = __float2bfloat16(v1);
                uint32_t hiw = (uint32_t)(*(uint16_t*)&h0b) | ((uint32_t)(*(uint16_t*)&h1b) << 16);
                uint32_t low = bfpack2(v0 - __bfloat162float(h0b), v1 - __bfloat162float(h1b));
                *(uint32_t*)&s_hi[hw*CPAD + cp*2] = hiw;
                *(uint32_t*)&s_lo[hw*CPAD + cp*2] = low;
            }
        }
        __syncthreads();

        for (int t = 0; t < 9; t++) {
            const int dr = t/3, dc = t%3;
            const int r0 = ((ph0 + dr)*34 + pw0 + dc)*CPAD;
            const int r1 = ((ph1 + dr)*34 + pw1 + dc)*CPAD;
            #pragma unroll
            for (int ks = 0; ks < 2; ks++) {
                uint4 bfr[8];
                const uint4* wp = wf + (size_t)(((t*2 + kh)*2 + ks)*8)*32 + lane;
                #pragma unroll
                for (int nt = 0; nt < 8; nt++) bfr[nt] = wp[nt*32];

                const int k = ks*16 + t2;
                uint32_t ah[4], al[4];
                ah[0] = *(const uint32_t*)&s_hi[r0 + k];
                ah[1] = *(const uint32_t*)&s_hi[r1 + k];
                ah[2] = *(const uint32_t*)&s_hi[r0 + k + 8];
                ah[3] = *(const uint32_t*)&s_hi[r1 + k + 8];
                al[0] = *(const uint32_t*)&s_lo[r0 + k];
                al[1] = *(const uint32_t*)&s_lo[r1 + k];
                al[2] = *(const uint32_t*)&s_lo[r0 + k + 8];
                al[3] = *(const uint32_t*)&s_lo[r1 + k + 8];

                #pragma unroll
                for (int nt = 0; nt < 8; nt++) {
                    mma_bf16(d[nt], ah, bfr[nt].x, bfr[nt].y);
                    mma_bf16(d[nt], al, bfr[nt].x, bfr[nt].y);
                    mma_bf16(d[nt], ah, bfr[nt].z, bfr[nt].w);
                }
            }
        }
    }
    __syncthreads();

    uint16_t* f_hi = s_buf;
    uint16_t* f_lo = s_buf + 128*FPAD;
    #pragma unroll
    for (int nt = 0; nt < 8; nt++) {
        int oc = nt*8 + t2;
        float b0v = s_b2[oc], b1v = s_b2[oc+1];
        float v00 = fmaxf(d[nt][0] + b0v, 0.f);
        float v01 = fmaxf(d[nt][1] + b1v, 0.f);
        float v10 = fmaxf(d[nt][2] + b0v, 0.f);
        float v11 = fmaxf(d[nt][3] + b1v, 0.f);
        __nv_bfloat16 h00 = __float2bfloat16(v00), h01 = __float2bfloat16(v01);
        __nv_bfloat16 h10 = __float2bfloat16(v10), h11 = __float2bfloat16(v11);
        *(uint32_t*)&f_hi[m0*FPAD + oc] =
            (uint32_t)(*(uint16_t*)&h00) | ((uint32_t)(*(uint16_t*)&h01) << 16);
        *(uint32_t*)&f_hi[m1*FPAD + oc] =
            (uint32_t)(*(uint16_t*)&h10) | ((uint32_t)(*(uint16_t*)&h11) << 16);
        *(uint32_t*)&f_lo[m0*FPAD + oc] =
            bfpack2(v00 - __bfloat162float(h00), v01 - __bfloat162float(h01));
        *(uint32_t*)&f_lo[m1*FPAD + oc] =
            bfpack2(v10 - __bfloat162float(h10), v11 - __bfloat162float(h11));
    }
    __syncthreads();

    float e[8][4];
    #pragma unroll
    for (int nt = 0; nt < 8; nt++)
        #pragma unroll
        for (int i = 0; i < 4; i++) e[nt][i] = 0.f;

    #pragma unroll
    for (int ks = 0; ks < 4; ks++) {
        uint4 bfr[8];
        const uint4* wp = fcf + (ks*8)*32 + lane;
        #pragma unroll
        for (int nt = 0; nt < 8; nt++) bfr[nt] = wp[nt*32];

        const int k = ks*16 + t2;
        uint32_t ah[4], al[4];
        ah[0] = *(const uint32_t*)&f_hi[m0*FPAD + k];
        ah[1] = *(const uint32_t*)&f_hi[m1*FPAD + k];
        ah[2] = *(const uint32_t*)&f_hi[m0*FPAD + k + 8];
        ah[3] = *(const uint32_t*)&f_hi[m1*FPAD + k + 8];
        al[0] = *(const uint32_t*)&f_lo[m0*FPAD + k];
        al[1] = *(const uint32_t*)&f_lo[m1*FPAD + k];
        al[2] = *(const uint32_t*)&f_lo[m0*FPAD + k + 8];
        al[3] = *(const uint32_t*)&f_lo[m1*FPAD + k + 8];

        #pragma unroll
        for (int nt = 0; nt < 8; nt++) {
            mma_bf16(e[nt], ah, bfr[nt].x, bfr[nt].y);
            mma_bf16(e[nt], al, bfr[nt].x, bfr[nt].y);
            mma_bf16(e[nt], ah, bfr[nt].z, bfr[nt].w);
        }
    }

    const size_t base = (size_t)b*64*HWSZ;
    const int p0 = (h0 + ph0)*WW + w0 + pw0;
    const int p1 = (h0 + ph1)*WW + w0 + pw1;
    #pragma unroll
    for (int nt = 0; nt < 8; nt++) {
        int oc = nt*8 + t2;
        size_t i00 = base + (size_t)oc*HWSZ + p0;
        size_t i01 = i00 + HWSZ;
        size_t i10 = base + (size_t)oc*HWSZ + p1;
        size_t i11 = i10 + HWSZ;
        out[i00] = e[nt][0] + s_fcb[oc]   + resid[i00];
        out[i01] = e[nt][1] + s_fcb[oc+1] + resid[i01];
        out[i10] = e[nt][2] + s_fcb[oc]   + resid[i10];
        out[i11] = e[nt][3] + s_fcb[oc+1] + resid[i11];
    }
}

// ---------------------------------------------------------------------------
extern "C" void kernel_launch(void* const* d_in, const int* in_sizes, int n_in,
                              void* d_out, int out_size)
{
    (void)in_sizes; (void)n_in; (void)out_size;
    const float* x     = (const float*)d_in[0];
    const float* ba_w1 = (const float*)d_in[1];
    const float* ba_b1 = (const float*)d_in[2];
    const float* ba_w2 = (const float*)d_in[3];
    const float* ba_b2 = (const float*)d_in[4];
    // d_in[5..12]: offset branch — dead code in the reference, skipped.
    const float* rk5w  = (const float*)d_in[13];
    const float* rk5b  = (const float*)d_in[14];
    const float* rk7w  = (const float*)d_in[15];
    const float* rk7b  = (const float*)d_in[16];
    const float* lk5w  = (const float*)d_in[17];
    const float* lk5b  = (const float*)d_in[18];
    const float* lk7w  = (const float*)d_in[19];
    const float* lk7b  = (const float*)d_in[20];
    const float* sfw   = (const float*)d_in[21];
    const float* sfb   = (const float*)d_in[22];
    const float* sfg   = (const float*)d_in[23];
    const float* sfbb  = (const float*)d_in[24];
    const float* sfm   = (const float*)d_in[25];
    const float* sfv   = (const float*)d_in[26];
    const float* fcw   = (const float*)d_in[27];
    const float* fcb   = (const float*)d_in[28];
    float* out = (float*)d_out;

    float *pFus, *pWeff, *pBeff, *pB2;
    uint4 *pWf, *pFcf, *pWf1;
    cudaGetSymbolAddress((void**)&pFus,  g_fusion);
    cudaGetSymbolAddress((void**)&pWeff, g_Weff);
    cudaGetSymbolAddress((void**)&pBeff, g_beff);
    cudaGetSymbolAddress((void**)&pB2,   g_b2);
    cudaGetSymbolAddress((void**)&pWf,   g_wf);
    cudaGetSymbolAddress((void**)&pFcf,  g_fcf);
    cudaGetSymbolAddress((void**)&pWf1,  g_wf1);

    build_weff<<<16, 256>>>(rk5w, rk5b, rk7w, rk7b, lk5w, lk5b, lk7w, lk7b);
    prep_b<<<1, 64>>>(sfb, sfg, sfbb, sfm, sfv);
    prep_frag<<<58, 256>>>(sfw, sfg, sfv, fcw, ba_w1);

    conv32_edge_mma<<<dim3(WW/32, HH/4, BB), 256>>>(x, pWf1, ba_b1, ba_w2, ba_b2);
    fusion_k<<<dim3(HWSZ/256, 2, BB), 256>>>(x, pWeff, pBeff, pFus);
    conv64fc_mma<<<dim3(WW/32, HH/4, BB), 256>>>(pFus, pWf, pB2, pFcf, fcb, x, out);
}

// round 14
// speedup vs baseline: 1.0633x; 1.0633x over previous
#include <cuda_runtime.h>
#include <cuda_bf16.h>
#include <cstdint>
#include <cstddef>

#define BB 4
#define HH 160
#define WW 160
#define HWSZ (HH*WW)
#define CPAD 40          // padded channel stride (u16) for conv staging
#define FPAD 72          // padded k stride (u16) for fc phase

typedef unsigned long long ull;

// ---------------- packed f32x2 helpers (fp32 kernels) ----------------------
__device__ __forceinline__ ull pk2(float lo, float hi) {
    ull r; asm("mov.b64 %0,{%1,%2};" : "=l"(r) : "f"(lo), "f"(hi)); return r;
}
__device__ __forceinline__ void upk2(ull v, float& lo, float& hi) {
    asm("mov.b64 {%0,%1},%2;" : "=f"(lo), "=f"(hi) : "l"(v));
}
__device__ __forceinline__ ull f2fma(ull a, ull b, ull c) {
    ull d; asm("fma.rn.f32x2 %0,%1,%2,%3;" : "=l"(d) : "l"(a), "l"(b), "l"(c)); return d;
}

// ---------------- bf16 mma.sync helpers ------------------------------------
__device__ __forceinline__ void mma_bf16(float d[4], const uint32_t a[4],
                                         uint32_t b0, uint32_t b1) {
    asm volatile(
        "mma.sync.aligned.m16n8k16.row.col.f32.bf16.bf16.f32 "
        "{%0,%1,%2,%3}, {%4,%5,%6,%7}, {%8,%9}, {%0,%1,%2,%3};"
        : "+f"(d[0]), "+f"(d[1]), "+f"(d[2]), "+f"(d[3])
        : "r"(a[0]), "r"(a[1]), "r"(a[2]), "r"(a[3]), "r"(b0), "r"(b1));
}
__device__ __forceinline__ uint32_t bfpack2(float x, float y) {
    __nv_bfloat162 h = __halves2bfloat162(__float2bfloat16(x), __float2bfloat16(y));
    return *(uint32_t*)&h;
}
__device__ __forceinline__ float bfunp_lo(uint32_t v) {
    __nv_bfloat162 h = *(__nv_bfloat162*)&v;
    return __bfloat162float(__low2bfloat16(h));
}
__device__ __forceinline__ float bfunp_hi(uint32_t v) {
    __nv_bfloat162 h = *(__nv_bfloat162*)&v;
    return __bfloat162float(__high2bfloat16(h));
}

// ---------------- scratch (device globals; no allocation allowed) ----------
__device__ __align__(128) float g_gmap[BB*HWSZ];
__device__ __align__(128) float g_smap[BB*HWSZ];
__device__ __align__(128) float g_fusion[BB*64*HWSZ];
__device__ __align__(128) float g_Weff[64*64];
__device__ __align__(128) float g_beff[64];
__device__ __align__(128) float g_b2[64];         // BN-folded bias
__device__ __align__(128) uint4 g_wf[9216];       // conv64 frags [t][kh][ks][nt8][lane]
__device__ __align__(128) uint4 g_fcf[1024];      // fc frags [ks][nt8][lane]
__device__ __align__(128) uint4 g_wf1[4608];      // conv32 frags [t][kh][ks][nt4][lane]

// ---------------- K0a: effective dyn1d weights (sum over K) ----------------
__global__ void build_weff(const float* __restrict__ rk5w, const float* __restrict__ rk5b,
                           const float* __restrict__ rk7w, const float* __restrict__ rk7b,
                           const float* __restrict__ lk5w, const float* __restrict__ lk5b,
                           const float* __restrict__ lk7w, const float* __restrict__ lk7b)
{
    int id = blockIdx.x*blockDim.x + threadIdx.x;
    if (id >= 64*64) return;
    int m = id >> 6, c = id & 63;
    const float* w; const float* bs; int K, o;
    if      (m < 16) { w = rk5w; bs = rk5b; K = 5; o = m;    }
    else if (m < 32) { w = rk7w; bs = rk7b; K = 7; o = m-16; }
    else if (m < 48) { w = lk5w; bs = lk5b; K = 5; o = m-32; }
    else             { w = lk7w; bs = lk7b; K = 7; o = m-48; }
    float acc = 0.f;
    for (int k = 0; k < K; k++) acc += w[(o*K + k)*64 + c];
    g_Weff[m*64 + c] = acc;
    if (c == 0) {
        float bacc = 0.f;
        for (int k = 0; k < K; k++) bacc += bs[o*K + k];
        g_beff[m] = bacc;
    }
}

// ---------------- K0b: BN-folded bias for conv64 ---------------------------
__global__ void prep_b(const float* __restrict__ b2s, const float* __restrict__ bg,
                       const float* __restrict__ bbta, const float* __restrict__ bm,
                       const float* __restrict__ bv)
{
    int id = blockIdx.x*blockDim.x + threadIdx.x;
    if (id < 64) {
        float scc = bg[id] * rsqrtf(bv[id] + 1e-5f);
        g_b2[id] = b2s[id]*scc + bbta[id] - bm[id]*scc;
    }
}

// ---------------- K0c: pack mma B-fragments (hi/lo split) ------------------
__global__ void prep_frag(const float* __restrict__ sfw, const float* __restrict__ bg,
                          const float* __restrict__ bv, const float* __restrict__ fcw,
                          const float* __restrict__ w1)
{
    int id = blockIdx.x*blockDim.x + threadIdx.x;
    if (id < 9216) {
        int lane = id & 31; int rem = id >> 5;
        int nt = rem & 7; rem >>= 3;
        int ks = rem & 1; rem >>= 1;
        int kh = rem & 1; int t = rem >> 1;
        int n  = nt*8 + (lane >> 2);
        int k0 = kh*32 + ks*16 + (lane & 3)*2;
        float sc = bg[n] * rsqrtf(bv[n] + 1e-5f);
        float w00 = sfw[(n*64 + k0    )*9 + t] * sc;
        float w01 = sfw[(n*64 + k0 + 1)*9 + t] * sc;
        float w08 = sfw[(n*64 + k0 + 8)*9 + t] * sc;
        float w09 = sfw[(n*64 + k0 + 9)*9 + t] * sc;
        __nv_bfloat16 h00 = __float2bfloat16(w00), h01 = __float2bfloat16(w01);
        __nv_bfloat16 h08 = __float2bfloat16(w08), h09 = __float2bfloat16(w09);
        uint4 rec;
        rec.x = (uint32_t)(*(uint16_t*)&h00) | ((uint32_t)(*(uint16_t*)&h01) << 16);
        rec.y = (uint32_t)(*(uint16_t*)&h08) | ((uint32_t)(*(uint16_t*)&h09) << 16);
        rec.z = bfpack2(w00 - __bfloat162float(h00), w01 - __bfloat162float(h01));
        rec.w = bfpack2(w08 - __bfloat162float(h08), w09 - __bfloat162float(h09));
        g_wf[id] = rec;
    } else if (id < 10240) {
        int fid = id - 9216;
        int lane = fid & 31; int rem = fid >> 5;
        int nt = rem & 7; int ks = rem >> 3;
        int n  = nt*8 + (lane >> 2);
        int k0 = ks*16 + (lane & 3)*2;
        float w00 = fcw[n*64 + k0    ];
        float w01 = fcw[n*64 + k0 + 1];
        float w08 = fcw[n*64 + k0 + 8];
        float w09 = fcw[n*64 + k0 + 9];
        __nv_bfloat16 h00 = __float2bfloat16(w00), h01 = __float2bfloat16(w01);
        __nv_bfloat16 h08 = __float2bfloat16(w08), h09 = __float2bfloat16(w09);
        uint4 rec;
        rec.x = (uint32_t)(*(uint16_t*)&h00) | ((uint32_t)(*(uint16_t*)&h01) << 16);
        rec.y = (uint32_t)(*(uint16_t*)&h08) | ((uint32_t)(*(uint16_t*)&h09) << 16);
        rec.z = bfpack2(w00 - __bfloat162float(h00), w01 - __bfloat162float(h01));
        rec.w = bfpack2(w08 - __bfloat162float(h08), w09 - __bfloat162float(h09));
        g_fcf[fid] = rec;
    } else if (id < 14848) {
        int fid = id - 10240;
        int lane = fid & 31; int rem = fid >> 5;
        int nt = rem & 3; rem >>= 2;
        int ks = rem & 1; rem >>= 1;
        int kh = rem & 1; int t = rem >> 1;
        int n  = nt*8 + (lane >> 2);          // oc 0..31
        int k0 = kh*32 + ks*16 + (lane & 3)*2;
        float w00 = w1[(n*64 + k0    )*9 + t];
        float w01 = w1[(n*64 + k0 + 1)*9 + t];
        float w08 = w1[(n*64 + k0 + 8)*9 + t];
        float w09 = w1[(n*64 + k0 + 9)*9 + t];
        __nv_bfloat16 h00 = __float2bfloat16(w00), h01 = __float2bfloat16(w01);
        __nv_bfloat16 h08 = __float2bfloat16(w08), h09 = __float2bfloat16(w09);
        uint4 rec;
        rec.x = (uint32_t)(*(uint16_t*)&h00) | ((uint32_t)(*(uint16_t*)&h01) << 16);
        rec.y = (uint32_t)(*(uint16_t*)&h08) | ((uint32_t)(*(uint16_t*)&h09) << 16);
        rec.z = bfpack2(w00 - __bfloat162float(h00), w01 - __bfloat162float(h01));
        rec.w = bfpack2(w08 - __bfloat162float(h08), w09 - __bfloat162float(h09));
        g_wf1[fid] = rec;
    }
}

// ---------------- K1: conv3x3<32> + sobel edge + attention via mma.sync ----
// (R12-proven version: separate edge block, CPAD padding, 2-MMA compensation)
__global__ __launch_bounds__(256)
void conv32_edge_mma(const float* __restrict__ x,
                     const uint4* __restrict__ wf1, const float* __restrict__ b1,
                     const float* __restrict__ baw2, const float* __restrict__ bab2)
{
    __shared__ __align__(16) uint16_t s_hi[204*CPAD];   // [6*34][40]
    __shared__ __align__(16) uint16_t s_lo[204*CPAD];
    __shared__ float s_ep[2][128], s_sp[2][128];
    __shared__ float s_b1[32], s_w2[32];

    const int tid = threadIdx.x;
    const int wid = tid >> 5, lane = tid & 31;
    const int g = lane >> 2, t2 = (lane & 3) * 2;
    const int b  = blockIdx.z;
    const int w0 = blockIdx.x*32, h0 = blockIdx.y*4;

    if (tid < 32) { s_b1[tid] = b1[tid]; s_w2[tid] = baw2[tid]; }

    const int m0 = wid*16 + g, m1 = m0 + 8;
    const int ph0 = m0 >> 5, pw0 = m0 & 31;
    const int ph1 = m1 >> 5, pw1 = m1 & 31;

    const int ep  = tid & 127;
    const int cig = tid >> 7;
    const int eph = ep >> 5, epw = ep & 31;

    float d[4][4];
    #pragma unroll
    for (int nt = 0; nt < 4; nt++)
        #pragma unroll
        for (int i = 0; i < 4; i++) d[nt][i] = 0.f;
    float edge_acc = 0.f, sum_acc = 0.f;

    for (int kh = 0; kh < 2; kh++) {
        if (kh) __syncthreads();
        #pragma unroll
        for (int it = 0; it < 13; it++) {
            int idx = tid + it*256;
            if (idx < 3264) {
                int hw = idx >> 4, cp = idx & 15;
                int h = hw / 34, w = hw % 34;
                int gh = h0 - 1 + h, gw = w0 - 1 + w;
                bool inb = (gh >= 0 && gh < HH && gw >= 0 && gw < WW);
                int ci = kh*32 + cp*2;
                const float* fp = x + ((size_t)(b*64 + ci))*HWSZ + (inb ? gh*WW + gw : 0);
                float v0 = inb ? fp[0] : 0.f;
                float v1 = inb ? fp[HWSZ] : 0.f;
                __nv_bfloat16 h0b = __float2bfloat16(v0);
                __nv_bfloat16 h1b = __float2bfloat16(v1);
                uint32_t hiw = (uint32_t)(*(uint16_t*)&h0b) | ((uint32_t)(*(uint16_t*)&h1b) << 16);
                uint32_t low = bfpack2(v0 - __bfloat162float(h0b), v1 - __bfloat162float(h1b));
                *(uint32_t*)&s_hi[hw*CPAD + cp*2] = hiw;
                *(uint32_t*)&s_lo[hw*CPAD + cp*2] = low;
            }
        }
        __syncthreads();

        // ---- edge (hi-only) + channel-sum (hi+lo) partials ----
        {
            float v[7][16];
            const int base_h = eph, base_w = epw;
            #pragma unroll
            for (int ppos = 0; ppos < 7; ppos++) {
                int dh, dw;
                if (ppos < 6) {
                    if (kh == 0) { dh = ppos >> 1; dw = (ppos & 1) * 2; }
                    else         { dh = (ppos & 1) * 2; dw = ppos >> 1; }
                } else { dh = 1; dw = 1; }
                int hw = (base_h + dh)*34 + (base_w + dw);
                const uint4* ph_ = (const uint4*)&s_hi[hw*CPAD + cig*16];
                #pragma unroll
                for (int q = 0; q < 2; q++) {
                    uint4 hv = ph_[q];
                    const uint32_t hw_[4] = {hv.x, hv.y, hv.z, hv.w};
                    #pragma unroll
                    for (int r = 0; r < 4; r++) {
                        v[ppos][q*8 + r*2    ] = bfunp_lo(hw_[r]);
                        v[ppos][q*8 + r*2 + 1] = bfunp_hi(hw_[r]);
                    }
                }
                if (ppos == 6) {   // center needs full precision for sumx
                    const uint4* pl_ = (const uint4*)&s_lo[hw*CPAD + cig*16];
                    #pragma unroll
                    for (int q = 0; q < 2; q++) {
                        uint4 lv = pl_[q];
                        const uint32_t lw_[4] = {lv.x, lv.y, lv.z, lv.w};
                        #pragma unroll
                        for (int r = 0; r < 4; r++) {
                            v[6][q*8 + r*2    ] += bfunp_lo(lw_[r]);
                            v[6][q*8 + r*2 + 1] += bfunp_hi(lw_[r]);
                        }
                    }
                }
            }
            float e = 0.f, s = 0.f;
            #pragma unroll
            for (int c = 0; c < 16; c++) {
                s += v[6][c];
                float gsum = (v[1][c] - v[0][c]) + 2.f*(v[3][c] - v[2][c]) + (v[5][c] - v[4][c]);
                e += fabsf(gsum);
            }
            edge_acc += e;
            sum_acc  += s;
        }

        // ---- conv MMAs: (ah+al)*bh ----
        for (int t = 0; t < 9; t++) {
            const int dr = t/3, dc = t%3;
            const int r0 = ((ph0 + dr)*34 + pw0 + dc)*CPAD;
            const int r1 = ((ph1 + dr)*34 + pw1 + dc)*CPAD;
            #pragma unroll
            for (int ks = 0; ks < 2; ks++) {
                uint2 bfr[4];
                const uint2* wp = (const uint2*)(wf1 + (size_t)(((t*2 + kh)*2 + ks)*4)*32 + lane);
                #pragma unroll
                for (int nt = 0; nt < 4; nt++) bfr[nt] = wp[nt*64];

                const int k = ks*16 + t2;
                uint32_t ah[4], al[4];
                ah[0] = *(const uint32_t*)&s_hi[r0 + k];
                ah[1] = *(const uint32_t*)&s_hi[r1 + k];
                ah[2] = *(const uint32_t*)&s_hi[r0 + k + 8];
                ah[3] = *(const uint32_t*)&s_hi[r1 + k + 8];
                al[0] = *(const uint32_t*)&s_lo[r0 + k];
                al[1] = *(const uint32_t*)&s_lo[r1 + k];
                al[2] = *(const uint32_t*)&s_lo[r0 + k + 8];
                al[3] = *(const uint32_t*)&s_lo[r1 + k + 8];

                #pragma unroll
                for (int nt = 0; nt < 4; nt++) {
                    mma_bf16(d[nt], ah, bfr[nt].x, bfr[nt].y);
                    mma_bf16(d[nt], al, bfr[nt].x, bfr[nt].y);
                }
            }
        }
    }

    s_ep[cig][ep] = edge_acc;
    s_sp[cig][ep] = sum_acc;

    float att0 = 0.f, att1 = 0.f;
    #pragma unroll
    for (int nt = 0; nt < 4; nt++) {
        int oc = nt*8 + t2;
        float b0v = s_b1[oc], b1v = s_b1[oc+1];
        float w0v = s_w2[oc], w1v = s_w2[oc+1];
        att0 += w0v*fmaxf(d[nt][0] + b0v, 0.f) + w1v*fmaxf(d[nt][1] + b1v, 0.f);
        att1 += w0v*fmaxf(d[nt][2] + b0v, 0.f) + w1v*fmaxf(d[nt][3] + b1v, 0.f);
    }
    att0 += __shfl_xor_sync(0xFFFFFFFF, att0, 1);
    att0 += __shfl_xor_sync(0xFFFFFFFF, att0, 2);
    att1 += __shfl_xor_sync(0xFFFFFFFF, att1, 1);
    att1 += __shfl_xor_sync(0xFFFFFFFF, att1, 2);
    __syncthreads();

    if ((lane & 3) == 0) {
        float bb = bab2[0];
        #pragma unroll
        for (int r = 0; r < 2; r++) {
            int m = r ? m1 : m0;
            float att = (r ? att1 : att0) + bb;
            float ed = (s_ep[0][m] + s_ep[1][m]) * (1.f/32.f);
            float sx =  s_sp[0][m] + s_sp[1][m];
            float z = att + ed;
            float a = 1.f / (1.f + expf(-z));
            float gv = 1.f + a;
            int mh = m >> 5, mw = m & 31;
            size_t pix = (size_t)b*HWSZ + (size_t)(h0 + mh)*WW + (w0 + mw);
            g_gmap[pix] = gv;
            g_smap[pix] = gv * sx;
        }
    }
}

// ---------------- K3: fusion GEMM, m-split x4 for occupancy ----------------
// Block: 16m x 256px. Thread: 4m x 4px (8 ull accs, ~70 regs -> 3 blocks/SM).
__global__ __launch_bounds__(256)
void fusion_k(const float* __restrict__ in, const float* __restrict__ wsrc,
              const float* __restrict__ bsrc, float* __restrict__ outp)
{
    __shared__ __align__(16) float s_w[64][16];   // [ci][m-quarter], 4KB
    __shared__ float s_b[16];
    const int tid = threadIdx.x;
    const int ms  = blockIdx.y;          // m-split 0..3
    const int b   = blockIdx.z;
    for (int i = tid; i < 1024; i += 256) {
        int ci = i >> 4, m = i & 15;
        s_w[ci][m] = wsrc[(ms*16 + m)*64 + ci];
    }
    if (tid < 16) s_b[tid] = bsrc[ms*16 + tid];
    __syncthreads();

    const int mg    = tid >> 6;          // 0..3
    const int mbase = mg*4;
    const int slot  = tid & 63;
    const int pix   = blockIdx.x*256 + slot*4;
    const float* basep = in + (size_t)b*64*HWSZ + pix;

    ull acc[2][4];
    #pragma unroll
    for (int m = 0; m < 2; m++)
        #pragma unroll
        for (int p = 0; p < 4; p++) acc[m][p] = 0ULL;

    float4 xv[4];
    #pragma unroll
    for (int j = 0; j < 4; j++)
        xv[j] = *(const float4*)(basep + (size_t)j*HWSZ);

    #pragma unroll 1
    for (int c4 = 0; c4 < 16; c4++) {
        float4 xn[4];
        if (c4 < 15) {
            const float* bp = basep + (size_t)(c4+1)*4*HWSZ;
            #pragma unroll
            for (int j = 0; j < 4; j++)
                xn[j] = *(const float4*)(bp + (size_t)j*HWSZ);
        }
        #pragma unroll
        for (int j = 0; j < 4; j++) {
            ull xd0 = pk2(xv[j].x, xv[j].x);
            ull xd1 = pk2(xv[j].y, xv[j].y);
            ull xd2 = pk2(xv[j].z, xv[j].z);
            ull xd3 = pk2(xv[j].w, xv[j].w);
            const ulonglong2* wp = (const ulonglong2*)&s_w[c4*4 + j][mbase];
            ulonglong2 wA = wp[0];
            acc[0][0]=f2fma(wA.x,xd0,acc[0][0]); acc[0][1]=f2fma(wA.x,xd1,acc[0][1]);
            acc[0][2]=f2fma(wA.x,xd2,acc[0][2]); acc[0][3]=f2fma(wA.x,xd3,acc[0][3]);
            acc[1][0]=f2fma(wA.y,xd0,acc[1][0]); acc[1][1]=f2fma(wA.y,xd1,acc[1][1]);
            acc[1][2]=f2fma(wA.y,xd2,acc[1][2]); acc[1][3]=f2fma(wA.y,xd3,acc[1][3]);
        }
        if (c4 < 15) {
            #pragma unroll
            for (int j = 0; j < 4; j++) xv[j] = xn[j];
        }
    }

    float4 gv = *(const float4*)&g_gmap[(size_t)b*HWSZ + pix];
    float4 sv = *(const float4*)&g_smap[(size_t)b*HWSZ + pix];
    float gs[4] = {gv.x, gv.y, gv.z, gv.w};
    float ss[4] = {sv.x, sv.y, sv.z, sv.w};
    #pragma unroll
    for (int mp = 0; mp < 2; mp++) {
        int ch = ms*16 + mbase + 2*mp;
        float b0 = s_b[mbase + 2*mp], b1 = s_b[mbase + 2*mp + 1];
        float lo[4], hi[4];
        #pragma unroll
        for (int p = 0; p < 4; p++) {
            float alo, ahi;
            upk2(acc[mp][p], alo, ahi);
            lo[p] = ss[p] * (gs[p]*alo + b0);
            hi[p] = ss[p] * (gs[p]*ahi + b1);
        }
        float4 vlo = {lo[0], lo[1], lo[2], lo[3]};
        float4 vhi = {hi[0], hi[1], hi[2], hi[3]};
        *(float4*)&outp[((size_t)(b*64 + ch  ))*HWSZ + pix] = vlo;
        *(float4*)&outp[((size_t)(b*64 + ch+1))*HWSZ + pix] = vhi;
    }
}

// ---------------- K4: conv3x3<64> + fc + residual via bf16 mma.sync --------
// Padded strides: conv CPAD=40 (80B rows), fc FPAD=72 (144B rows) -> no conflicts.
__global__ __launch_bounds__(256)
void conv64fc_mma(const float* __restrict__ fus,
                  const uint4* __restrict__ wf, const float* __restrict__ b2,
                  const uint4* __restrict__ fcf, const float* __restrict__ fcb,
                  const float* __restrict__ resid, float* __restrict__ out)
{
    __shared__ __align__(16) uint16_t s_buf[2*128*FPAD];   // 36864B
    __shared__ float s_b2[64], s_fcb[64];

    const int tid = threadIdx.x;
    const int wid = tid >> 5, lane = tid & 31;
    const int g = lane >> 2, t2 = (lane & 3) * 2;
    const int b  = blockIdx.z;
    const int w0 = blockIdx.x*32, h0 = blockIdx.y*4;

    if (tid < 64) { s_b2[tid] = b2[tid]; s_fcb[tid] = fcb[tid]; }

    uint16_t* s_hi = s_buf;
    uint16_t* s_lo = s_buf + 128*FPAD;

    const int m0 = wid*16 + g, m1 = m0 + 8;
    const int ph0 = m0 >> 5, pw0 = m0 & 31;
    const int ph1 = m1 >> 5, pw1 = m1 & 31;

    float d[8][4];
    #pragma unroll
    for (int nt = 0; nt < 8; nt++)
        #pragma unroll
        for (int i = 0; i < 4; i++) d[nt][i] = 0.f;

    for (int kh = 0; kh < 2; kh++) {
        if (kh) __syncthreads();
        #pragma unroll
        for (int it = 0; it < 13; it++) {
            int idx = tid + it*256;
            if (idx < 3264) {
                int hw = idx >> 4, cp = idx & 15;
                int h = hw / 34, w = hw % 34;
                int gh = h0 - 1 + h, gw = w0 - 1 + w;
                bool inb = (gh >= 0 && gh < HH && gw >= 0 && gw < WW);
                int ci = kh*32 + cp*2;
                const float* fp = fus + ((size_t)(b*64 + ci))*HWSZ + (inb ? gh*WW + gw : 0);
                float v0 = inb ? fp[0] : 0.f;
                float v1 = inb ? fp[HWSZ] : 0.f;
                __nv_bfloat16 h0b = __float2bfloat16(v0);
                __nv_bfloat16 h1b = __float2bfloat16(v1);
                uint32_t hiw = (uint32_t)(*(uint16_t*)&h0b) | ((uint32_t)(*(uint16_t*)&h1b) << 16);
                uint32_t low = bfpack2(v0 - __bfloat162float(h0b), v1 - __bfloat162float(h1b));
                *(uint32_t*)&s_hi[hw*CPAD + cp*2] = hiw;
                *(uint32_t*)&s_lo[hw*CPAD + cp*2] = low;
            }
        }
        __syncthreads();

        for (int t = 0; t < 9; t++) {
            const int dr = t/3, dc = t%3;
            const int r0 = ((ph0 + dr)*34 + pw0 + dc)*CPAD;
            const int r1 = ((ph1 + dr)*34 + pw1 + dc)*CPAD;
            #pragma unroll
            for (int ks = 0; ks < 2; ks++) {
                uint4 bfr[8];
                const uint4* wp = wf + (size_t)(((t*2 + kh)*2 + ks)*8)*32 + lane;
                #pragma unroll
                for (int nt = 0; nt < 8; nt++) bfr[nt] = wp[nt*32];

                const int k = ks*16 + t2;
                uint32_t ah[4], al[4];
                ah[0] = *(const uint32_t*)&s_hi[r0 + k];
                ah[1] = *(const uint32_t*)&s_hi[r1 + k];
                ah[2] = *(const uint32_t*)&s_hi[r0 + k + 8];
                ah[3] = *(const uint32_t*)&s_hi[r1 + k + 8];
                al[0] = *(const uint32_t*)&s_lo[r0 + k];
                al[1] = *(const uint32_t*)&s_lo[r1 + k];
                al[2] = *(const uint32_t*)&s_lo[r0 + k + 8];
                al[3] = *(const uint32_t*)&s_lo[r1 + k + 8];

                #pragma unroll
                for (int nt = 0; nt < 8; nt++) {
                    mma_bf16(d[nt], ah, bfr[nt].x, bfr[nt].y);
                    mma_bf16(d[nt], al, bfr[nt].x, bfr[nt].y);
                    mma_bf16(d[nt], ah, bfr[nt].z, bfr[nt].w);
                }
            }
        }
    }
    __syncthreads();

    uint16_t* f_hi = s_buf;
    uint16_t* f_lo = s_buf + 128*FPAD;
    #pragma unroll
    for (int nt = 0; nt < 8; nt++) {
        int oc = nt*8 + t2;
        float b0v = s_b2[oc], b1v = s_b2[oc+1];
        float v00 = fmaxf(d[nt][0] + b0v, 0.f);
        float v01 = fmaxf(d[nt][1] + b1v, 0.f);
        float v10 = fmaxf(d[nt][2] + b0v, 0.f);
        float v11 = fmaxf(d[nt][3] + b1v, 0.f);
        __nv_bfloat16 h00 = __float2bfloat16(v00), h01 = __float2bfloat16(v01);
        __nv_bfloat16 h10 = __float2bfloat16(v10), h11 = __float2bfloat16(v11);
        *(uint32_t*)&f_hi[m0*FPAD + oc] =
            (uint32_t)(*(uint16_t*)&h00) | ((uint32_t)(*(uint16_t*)&h01) << 16);
        *(uint32_t*)&f_hi[m1*FPAD + oc] =
            (uint32_t)(*(uint16_t*)&h10) | ((uint32_t)(*(uint16_t*)&h11) << 16);
        *(uint32_t*)&f_lo[m0*FPAD + oc] =
            bfpack2(v00 - __bfloat162float(h00), v01 - __bfloat162float(h01));
        *(uint32_t*)&f_lo[m1*FPAD + oc] =
            bfpack2(v10 - __bfloat162float(h10), v11 - __bfloat162float(h11));
    }
    __syncthreads();

    float e[8][4];
    #pragma unroll
    for (int nt = 0; nt < 8; nt++)
        #pragma unroll
        for (int i = 0; i < 4; i++) e[nt][i] = 0.f;

    #pragma unroll
    for (int ks = 0; ks < 4; ks++) {
        uint4 bfr[8];
        const uint4* wp = fcf + (ks*8)*32 + lane;
        #pragma unroll
        for (int nt = 0; nt < 8; nt++) bfr[nt] = wp[nt*32];

        const int k = ks*16 + t2;
        uint32_t ah[4], al[4];
        ah[0] = *(const uint32_t*)&f_hi[m0*FPAD + k];
        ah[1] = *(const uint32_t*)&f_hi[m1*FPAD + k];
        ah[2] = *(const uint32_t*)&f_hi[m0*FPAD + k + 8];
        ah[3] = *(const uint32_t*)&f_hi[m1*FPAD + k + 8];
        al[0] = *(const uint32_t*)&f_lo[m0*FPAD + k];
        al[1] = *(const uint32_t*)&f_lo[m1*FPAD + k];
        al[2] = *(const uint32_t*)&f_lo[m0*FPAD + k + 8];
        al[3] = *(const uint32_t*)&f_lo[m1*FPAD + k + 8];

        #pragma unroll
        for (int nt = 0; nt < 8; nt++) {
            mma_bf16(e[nt], ah, bfr[nt].x, bfr[nt].y);
            mma_bf16(e[nt], al, bfr[nt].x, bfr[nt].y);
            mma_bf16(e[nt], ah, bfr[nt].z, bfr[nt].w);
        }
    }

    const size_t base = (size_t)b*64*HWSZ;
    const int p0 = (h0 + ph0)*WW + w0 + pw0;
    const int p1 = (h0 + ph1)*WW + w0 + pw1;
    #pragma unroll
    for (int nt = 0; nt < 8; nt++) {
        int oc = nt*8 + t2;
        size_t i00 = base + (size_t)oc*HWSZ + p0;
        size_t i01 = i00 + HWSZ;
        size_t i10 = base + (size_t)oc*HWSZ + p1;
        size_t i11 = i10 + HWSZ;
        out[i00] = e[nt][0] + s_fcb[oc]   + resid[i00];
        out[i01] = e[nt][1] + s_fcb[oc+1] + resid[i01];
        out[i10] = e[nt][2] + s_fcb[oc]   + resid[i10];
        out[i11] = e[nt][3] + s_fcb[oc+1] + resid[i11];
    }
}

// ---------------------------------------------------------------------------
extern "C" void kernel_launch(void* const* d_in, const int* in_sizes, int n_in,
                              void* d_out, int out_size)
{
    (void)in_sizes; (void)n_in; (void)out_size;
    const float* x     = (const float*)d_in[0];
    const float* ba_w1 = (const float*)d_in[1];
    const float* ba_b1 = (const float*)d_in[2];
    const float* ba_w2 = (const float*)d_in[3];
    const float* ba_b2 = (const float*)d_in[4];
    // d_in[5..12]: offset branch — dead code in the reference, skipped.
    const float* rk5w  = (const float*)d_in[13];
    const float* rk5b  = (const float*)d_in[14];
    const float* rk7w  = (const float*)d_in[15];
    const float* rk7b  = (const float*)d_in[16];
    const float* lk5w  = (const float*)d_in[17];
    const float* lk5b  = (const float*)d_in[18];
    const float* lk7w  = (const float*)d_in[19];
    const float* lk7b  = (const float*)d_in[20];
    const float* sfw   = (const float*)d_in[21];
    const float* sfb   = (const float*)d_in[22];
    const float* sfg   = (const float*)d_in[23];
    const float* sfbb  = (const float*)d_in[24];
    const float* sfm   = (const float*)d_in[25];
    const float* sfv   = (const float*)d_in[26];
    const float* fcw   = (const float*)d_in[27];
    const float* fcb   = (const float*)d_in[28];
    float* out = (float*)d_out;

    float *pFus, *pWeff, *pBeff, *pB2;
    uint4 *pWf, *pFcf, *pWf1;
    cudaGetSymbolAddress((void**)&pFus,  g_fusion);
    cudaGetSymbolAddress((void**)&pWeff, g_Weff);
    cudaGetSymbolAddress((void**)&pBeff, g_beff);
    cudaGetSymbolAddress((void**)&pB2,   g_b2);
    cudaGetSymbolAddress((void**)&pWf,   g_wf);
    cudaGetSymbolAddress((void**)&pFcf,  g_fcf);
    cudaGetSymbolAddress((void**)&pWf1,  g_wf1);

    build_weff<<<16, 256>>>(rk5w, rk5b, rk7w, rk7b, lk5w, lk5b, lk7w, lk7b);
    prep_b<<<1, 64>>>(sfb, sfg, sfbb, sfm, sfv);
    prep_frag<<<58, 256>>>(sfw, sfg, sfv, fcw, ba_w1);

    conv32_edge_mma<<<dim3(WW/32, HH/4, BB), 256>>>(x, pWf1, ba_b1, ba_w2, ba_b2);
    fusion_k<<<dim3(HWSZ/256, 4, BB), 256>>>(x, pWeff, pBeff, pFus);
    conv64fc_mma<<<dim3(WW/32, HH/4, BB), 256>>>(pFus, pWf, pB2, pFcf, fcb, x, out);
}

// round 15
// speedup vs baseline: 1.3453x; 1.2652x over previous
#include <cuda_runtime.h>
#include <cuda_bf16.h>
#include <cstdint>
#include <cstddef>

#define BB 4
#define HH 160
#define WW 160
#define HWSZ (HH*WW)
#define CPAD 40          // padded channel stride (u16) for conv staging
#define FPAD 72          // padded k stride (u16) for fc phase
#define XPXS 33          // u32 stride per pixel in transpose smem

typedef unsigned long long ull;

// ---------------- packed f32x2 helpers (fp32 kernels) ----------------------
__device__ __forceinline__ ull pk2(float lo, float hi) {
    ull r; asm("mov.b64 %0,{%1,%2};" : "=l"(r) : "f"(lo), "f"(hi)); return r;
}
__device__ __forceinline__ void upk2(ull v, float& lo, float& hi) {
    asm("mov.b64 {%0,%1},%2;" : "=f"(lo), "=f"(hi) : "l"(v));
}
__device__ __forceinline__ ull f2fma(ull a, ull b, ull c) {
    ull d; asm("fma.rn.f32x2 %0,%1,%2,%3;" : "=l"(d) : "l"(a), "l"(b), "l"(c)); return d;
}

// ---------------- bf16 mma.sync helpers ------------------------------------
__device__ __forceinline__ void mma_bf16(float d[4], const uint32_t a[4],
                                         uint32_t b0, uint32_t b1) {
    asm volatile(
        "mma.sync.aligned.m16n8k16.row.col.f32.bf16.bf16.f32 "
        "{%0,%1,%2,%3}, {%4,%5,%6,%7}, {%8,%9}, {%0,%1,%2,%3};"
        : "+f"(d[0]), "+f"(d[1]), "+f"(d[2]), "+f"(d[3])
        : "r"(a[0]), "r"(a[1]), "r"(a[2]), "r"(a[3]), "r"(b0), "r"(b1));
}
__device__ __forceinline__ uint32_t bfpack2(float x, float y) {
    __nv_bfloat162 h = __halves2bfloat162(__float2bfloat16(x), __float2bfloat16(y));
    return *(uint32_t*)&h;
}
__device__ __forceinline__ float bfunp_lo(uint32_t v) {
    __nv_bfloat162 h = *(__nv_bfloat162*)&v;
    return __bfloat162float(__low2bfloat16(h));
}
__device__ __forceinline__ float bfunp_hi(uint32_t v) {
    __nv_bfloat162 h = *(__nv_bfloat162*)&v;
    return __bfloat162float(__high2bfloat16(h));
}
__device__ __forceinline__ uint32_t packbf(float v0, float v1, uint32_t& lo) {
    __nv_bfloat16 h0 = __float2bfloat16(v0);
    __nv_bfloat16 h1 = __float2bfloat16(v1);
    lo = bfpack2(v0 - __bfloat162float(h0), v1 - __bfloat162float(h1));
    return (uint32_t)(*(uint16_t*)&h0) | ((uint32_t)(*(uint16_t*)&h1) << 16);
}

// ---------------- scratch (device globals; no allocation allowed) ----------
__device__ __align__(128) float g_gmap[BB*HWSZ];
__device__ __align__(128) float g_smap[BB*HWSZ];
__device__ __align__(128) float g_Weff[64*64];
__device__ __align__(128) float g_beff[64];
__device__ __align__(128) float g_b2[64];
__device__ __align__(128) uint4 g_wf[9216];       // conv64 frags
__device__ __align__(128) uint4 g_fcf[1024];      // fc frags
__device__ __align__(128) uint4 g_wf1[4608];      // conv32 frags
__device__ __align__(128) uint16_t g_xh[(size_t)BB*HWSZ*64];  // x bf16 hi, ch-last
__device__ __align__(128) uint16_t g_xl[(size_t)BB*HWSZ*64];  // x bf16 lo
__device__ __align__(128) uint16_t g_fh[(size_t)BB*HWSZ*64];  // fusion hi, ch-last
__device__ __align__(128) uint16_t g_fl[(size_t)BB*HWSZ*64];  // fusion lo

// ---------------- K0a: effective dyn1d weights (sum over K) ----------------
__global__ void build_weff(const float* __restrict__ rk5w, const float* __restrict__ rk5b,
                           const float* __restrict__ rk7w, const float* __restrict__ rk7b,
                           const float* __restrict__ lk5w, const float* __restrict__ lk5b,
                           const float* __restrict__ lk7w, const float* __restrict__ lk7b)
{
    int id = blockIdx.x*blockDim.x + threadIdx.x;
    if (id >= 64*64) return;
    int m = id >> 6, c = id & 63;
    const float* w; const float* bs; int K, o;
    if      (m < 16) { w = rk5w; bs = rk5b; K = 5; o = m;    }
    else if (m < 32) { w = rk7w; bs = rk7b; K = 7; o = m-16; }
    else if (m < 48) { w = lk5w; bs = lk5b; K = 5; o = m-32; }
    else             { w = lk7w; bs = lk7b; K = 7; o = m-48; }
    float acc = 0.f;
    for (int k = 0; k < K; k++) acc += w[(o*K + k)*64 + c];
    g_Weff[m*64 + c] = acc;
    if (c == 0) {
        float bacc = 0.f;
        for (int k = 0; k < K; k++) bacc += bs[o*K + k];
        g_beff[m] = bacc;
    }
}

// ---------------- K0b: BN-folded bias for conv64 ---------------------------
__global__ void prep_b(const float* __restrict__ b2s, const float* __restrict__ bg,
                       const float* __restrict__ bbta, const float* __restrict__ bm,
                       const float* __restrict__ bv)
{
    int id = blockIdx.x*blockDim.x + threadIdx.x;
    if (id < 64) {
        float scc = bg[id] * rsqrtf(bv[id] + 1e-5f);
        g_b2[id] = b2s[id]*scc + bbta[id] - bm[id]*scc;
    }
}

// ---------------- K0c: pack mma B-fragments (hi/lo split) ------------------
__global__ void prep_frag(const float* __restrict__ sfw, const float* __restrict__ bg,
                          const float* __restrict__ bv, const float* __restrict__ fcw,
                          const float* __restrict__ w1)
{
    int id = blockIdx.x*blockDim.x + threadIdx.x;
    if (id < 9216) {
        int lane = id & 31; int rem = id >> 5;
        int nt = rem & 7; rem >>= 3;
        int ks = rem & 1; rem >>= 1;
        int kh = rem & 1; int t = rem >> 1;
        int n  = nt*8 + (lane >> 2);
        int k0 = kh*32 + ks*16 + (lane & 3)*2;
        float sc = bg[n] * rsqrtf(bv[n] + 1e-5f);
        float w00 = sfw[(n*64 + k0    )*9 + t] * sc;
        float w01 = sfw[(n*64 + k0 + 1)*9 + t] * sc;
        float w08 = sfw[(n*64 + k0 + 8)*9 + t] * sc;
        float w09 = sfw[(n*64 + k0 + 9)*9 + t] * sc;
        uint4 rec;
        rec.x = packbf(w00, w01, rec.z);
        rec.y = packbf(w08, w09, rec.w);
        g_wf[id] = rec;
    } else if (id < 10240) {
        int fid = id - 9216;
        int lane = fid & 31; int rem = fid >> 5;
        int nt = rem & 7; int ks = rem >> 3;
        int n  = nt*8 + (lane >> 2);
        int k0 = ks*16 + (lane & 3)*2;
        uint4 rec;
        rec.x = packbf(fcw[n*64 + k0    ], fcw[n*64 + k0 + 1], rec.z);
        rec.y = packbf(fcw[n*64 + k0 + 8], fcw[n*64 + k0 + 9], rec.w);
        g_fcf[fid] = rec;
    } else if (id < 14848) {
        int fid = id - 10240;
        int lane = fid & 31; int rem = fid >> 5;
        int nt = rem & 3; rem >>= 2;
        int ks = rem & 1; rem >>= 1;
        int kh = rem & 1; int t = rem >> 1;
        int n  = nt*8 + (lane >> 2);
        int k0 = kh*32 + ks*16 + (lane & 3)*2;
        uint4 rec;
        rec.x = packbf(w1[(n*64 + k0    )*9 + t], w1[(n*64 + k0 + 1)*9 + t], rec.z);
        rec.y = packbf(w1[(n*64 + k0 + 8)*9 + t], w1[(n*64 + k0 + 9)*9 + t], rec.w);
        g_wf1[fid] = rec;
    }
}

// ---------------- K0d: transpose x -> channel-last bf16 hi/lo --------------
// Block handles 128 pixels. Conflict-free smem transpose (XPXS=33 u32 rows).
__global__ __launch_bounds__(256)
void xpose_k(const float* __restrict__ x)
{
    __shared__ uint32_t s_h[128*XPXS];
    __shared__ uint32_t s_l[128*XPXS];
    const int tid = threadIdx.x;
    const int b   = blockIdx.y;
    const int px0 = blockIdx.x*128;
    const int px  = tid & 127;
    const int hf  = tid >> 7;

    #pragma unroll
    for (int c2 = 0; c2 < 16; c2++) {
        int c = hf*32 + c2*2;
        const float* fp = x + ((size_t)(b*64 + c))*HWSZ + px0 + px;
        float v0 = fp[0];
        float v1 = fp[HWSZ];
        uint32_t lw;
        uint32_t hw = packbf(v0, v1, lw);
        s_h[px*XPXS + hf*16 + c2] = hw;
        s_l[px*XPXS + hf*16 + c2] = lw;
    }
    __syncthreads();

    uint32_t* xh32 = (uint32_t*)g_xh;
    uint32_t* xl32 = (uint32_t*)g_xl;
    #pragma unroll
    for (int k = 0; k < 4; k++) {
        int idx = tid + k*256;
        int p = idx >> 3, q = idx & 7;
        size_t ga = ((size_t)b*HWSZ + px0 + p)*32 + q*4;
        uint4 hv, lv;
        hv.x = s_h[p*XPXS + q*4    ]; hv.y = s_h[p*XPXS + q*4 + 1];
        hv.z = s_h[p*XPXS + q*4 + 2]; hv.w = s_h[p*XPXS + q*4 + 3];
        lv.x = s_l[p*XPXS + q*4    ]; lv.y = s_l[p*XPXS + q*4 + 1];
        lv.z = s_l[p*XPXS + q*4 + 2]; lv.w = s_l[p*XPXS + q*4 + 3];
        *(uint4*)&xh32[ga] = hv;
        *(uint4*)&xl32[ga] = lv;
    }
}

// ---------------- K1: conv3x3<32> + sobel edge + attention via mma.sync ----
// Staging now: coalesced uint4 copies from channel-last bf16 tensors.
__global__ __launch_bounds__(256)
void conv32_edge_mma(const uint4* __restrict__ wf1, const float* __restrict__ b1,
                     const float* __restrict__ baw2, const float* __restrict__ bab2)
{
    __shared__ __align__(16) uint16_t s_hi[204*CPAD];
    __shared__ __align__(16) uint16_t s_lo[204*CPAD];
    __shared__ float s_ep[2][128], s_sp[2][128];
    __shared__ float s_b1[32], s_w2[32];

    const int tid = threadIdx.x;
    const int wid = tid >> 5, lane = tid & 31;
    const int g = lane >> 2, t2 = (lane & 3) * 2;
    const int b  = blockIdx.z;
    const int w0 = blockIdx.x*32, h0 = blockIdx.y*4;

    if (tid < 32) { s_b1[tid] = b1[tid]; s_w2[tid] = baw2[tid]; }

    const int m0 = wid*16 + g, m1 = m0 + 8;
    const int ph0 = m0 >> 5, pw0 = m0 & 31;
    const int ph1 = m1 >> 5, pw1 = m1 & 31;

    const int ep  = tid & 127;
    const int cig = tid >> 7;
    const int eph = ep >> 5, epw = ep & 31;

    const uint32_t* xh32 = (const uint32_t*)g_xh + (size_t)b*HWSZ*32;
    const uint32_t* xl32 = (const uint32_t*)g_xl + (size_t)b*HWSZ*32;

    float d[4][4];
    #pragma unroll
    for (int nt = 0; nt < 4; nt++)
        #pragma unroll
        for (int i = 0; i < 4; i++) d[nt][i] = 0.f;
    float edge_acc = 0.f, sum_acc = 0.f;

    for (int kh = 0; kh < 2; kh++) {
        if (kh) __syncthreads();
        #pragma unroll
        for (int it = 0; it < 4; it++) {
            int idx = tid + it*256;
            if (idx < 816) {
                int pos = idx >> 2, q = idx & 3;
                int h = pos/34, w = pos%34;
                int gh = h0 - 1 + h, gw = w0 - 1 + w;
                bool inb = (gh >= 0 && gh < HH && gw >= 0 && gw < WW);
                uint4 hv = make_uint4(0,0,0,0), lv = make_uint4(0,0,0,0);
                if (inb) {
                    size_t ga = ((size_t)(gh*WW + gw))*32 + kh*16 + q*4;
                    hv = *(const uint4*)&xh32[ga];
                    lv = *(const uint4*)&xl32[ga];
                }
                *(uint4*)&s_hi[pos*CPAD + q*8] = hv;
                *(uint4*)&s_lo[pos*CPAD + q*8] = lv;
            }
        }
        __syncthreads();

        // ---- edge (hi-only) + channel-sum (hi+lo) partials ----
        {
            float v[7][16];
            const int base_h = eph, base_w = epw;
            #pragma unroll
            for (int ppos = 0; ppos < 7; ppos++) {
                int dh, dw;
                if (ppos < 6) {
                    if (kh == 0) { dh = ppos >> 1; dw = (ppos & 1) * 2; }
                    else         { dh = (ppos & 1) * 2; dw = ppos >> 1; }
                } else { dh = 1; dw = 1; }
                int hw = (base_h + dh)*34 + (base_w + dw);
                const uint4* ph_ = (const uint4*)&s_hi[hw*CPAD + cig*16];
                #pragma unroll
                for (int q = 0; q < 2; q++) {
                    uint4 hv = ph_[q];
                    const uint32_t hw_[4] = {hv.x, hv.y, hv.z, hv.w};
                    #pragma unroll
                    for (int r = 0; r < 4; r++) {
                        v[ppos][q*8 + r*2    ] = bfunp_lo(hw_[r]);
                        v[ppos][q*8 + r*2 + 1] = bfunp_hi(hw_[r]);
                    }
                }
                if (ppos == 6) {
                    const uint4* pl_ = (const uint4*)&s_lo[hw*CPAD + cig*16];
                    #pragma unroll
                    for (int q = 0; q < 2; q++) {
                        uint4 lv = pl_[q];
                        const uint32_t lw_[4] = {lv.x, lv.y, lv.z, lv.w};
                        #pragma unroll
                        for (int r = 0; r < 4; r++) {
                            v[6][q*8 + r*2    ] += bfunp_lo(lw_[r]);
                            v[6][q*8 + r*2 + 1] += bfunp_hi(lw_[r]);
                        }
                    }
                }
            }
            float e = 0.f, s = 0.f;
            #pragma unroll
            for (int c = 0; c < 16; c++) {
                s += v[6][c];
                float gsum = (v[1][c] - v[0][c]) + 2.f*(v[3][c] - v[2][c]) + (v[5][c] - v[4][c]);
                e += fabsf(gsum);
            }
            edge_acc += e;
            sum_acc  += s;
        }

        // ---- conv MMAs: (ah+al)*bh ----
        for (int t = 0; t < 9; t++) {
            const int dr = t/3, dc = t%3;
            const int r0 = ((ph0 + dr)*34 + pw0 + dc)*CPAD;
            const int r1 = ((ph1 + dr)*34 + pw1 + dc)*CPAD;
            #pragma unroll
            for (int ks = 0; ks < 2; ks++) {
                uint2 bfr[4];
                const uint2* wp = (const uint2*)(wf1 + (size_t)(((t*2 + kh)*2 + ks)*4)*32 + lane);
                #pragma unroll
                for (int nt = 0; nt < 4; nt++) bfr[nt] = wp[nt*64];

                const int k = ks*16 + t2;
                uint32_t ah[4], al[4];
                ah[0] = *(const uint32_t*)&s_hi[r0 + k];
                ah[1] = *(const uint32_t*)&s_hi[r1 + k];
                ah[2] = *(const uint32_t*)&s_hi[r0 + k + 8];
                ah[3] = *(const uint32_t*)&s_hi[r1 + k + 8];
                al[0] = *(const uint32_t*)&s_lo[r0 + k];
                al[1] = *(const uint32_t*)&s_lo[r1 + k];
                al[2] = *(const uint32_t*)&s_lo[r0 + k + 8];
                al[3] = *(const uint32_t*)&s_lo[r1 + k + 8];

                #pragma unroll
                for (int nt = 0; nt < 4; nt++) {
                    mma_bf16(d[nt], ah, bfr[nt].x, bfr[nt].y);
                    mma_bf16(d[nt], al, bfr[nt].x, bfr[nt].y);
                }
            }
        }
    }

    s_ep[cig][ep] = edge_acc;
    s_sp[cig][ep] = sum_acc;

    float att0 = 0.f, att1 = 0.f;
    #pragma unroll
    for (int nt = 0; nt < 4; nt++) {
        int oc = nt*8 + t2;
        float b0v = s_b1[oc], b1v = s_b1[oc+1];
        float w0v = s_w2[oc], w1v = s_w2[oc+1];
        att0 += w0v*fmaxf(d[nt][0] + b0v, 0.f) + w1v*fmaxf(d[nt][1] + b1v, 0.f);
        att1 += w0v*fmaxf(d[nt][2] + b0v, 0.f) + w1v*fmaxf(d[nt][3] + b1v, 0.f);
    }
    att0 += __shfl_xor_sync(0xFFFFFFFF, att0, 1);
    att0 += __shfl_xor_sync(0xFFFFFFFF, att0, 2);
    att1 += __shfl_xor_sync(0xFFFFFFFF, att1, 1);
    att1 += __shfl_xor_sync(0xFFFFFFFF, att1, 2);
    __syncthreads();

    if ((lane & 3) == 0) {
        float bb = bab2[0];
        #pragma unroll
        for (int r = 0; r < 2; r++) {
            int m = r ? m1 : m0;
            float att = (r ? att1 : att0) + bb;
            float ed = (s_ep[0][m] + s_ep[1][m]) * (1.f/32.f);
            float sx =  s_sp[0][m] + s_sp[1][m];
            float z = att + ed;
            float a = 1.f / (1.f + expf(-z));
            float gv = 1.f + a;
            int mh = m >> 5, mw = m & 31;
            size_t pix = (size_t)b*HWSZ + (size_t)(h0 + mh)*WW + (w0 + mw);
            g_gmap[pix] = gv;
            g_smap[pix] = gv * sx;
        }
    }
}

// ---------------- K3: fusion GEMM (R12 2-way m-split) -> bf16 ch-last ------
__global__ __launch_bounds__(256)
void fusion_k(const float* __restrict__ in, const float* __restrict__ wsrc,
              const float* __restrict__ bsrc)
{
    __shared__ __align__(16) float s_w[64][32];
    __shared__ float s_b[32];
    const int tid = threadIdx.x;
    const int ms  = blockIdx.y;
    const int b   = blockIdx.z;
    for (int i = tid; i < 2048; i += 256) {
        int ci = i >> 5, m = i & 31;
        s_w[ci][m] = wsrc[(ms*32 + m)*64 + ci];
    }
    if (tid < 32) s_b[tid] = bsrc[ms*32 + tid];
    __syncthreads();

    const int mg    = tid >> 6;
    const int mbase = mg*8;
    const int slot  = tid & 63;
    const int pix   = blockIdx.x*256 + slot*4;
    const float* basep = in + (size_t)b*64*HWSZ + pix;

    ull acc[4][4];
    #pragma unroll
    for (int m = 0; m < 4; m++)
        #pragma unroll
        for (int p = 0; p < 4; p++) acc[m][p] = 0ULL;

    float4 xv[4];
    #pragma unroll
    for (int j = 0; j < 4; j++)
        xv[j] = *(const float4*)(basep + (size_t)j*HWSZ);

    #pragma unroll 1
    for (int c4 = 0; c4 < 16; c4++) {
        float4 xn[4];
        if (c4 < 15) {
            const float* bp = basep + (size_t)(c4+1)*4*HWSZ;
            #pragma unroll
            for (int j = 0; j < 4; j++)
                xn[j] = *(const float4*)(bp + (size_t)j*HWSZ);
        }
        #pragma unroll
        for (int j = 0; j < 4; j++) {
            ull xd0 = pk2(xv[j].x, xv[j].x);
            ull xd1 = pk2(xv[j].y, xv[j].y);
            ull xd2 = pk2(xv[j].z, xv[j].z);
            ull xd3 = pk2(xv[j].w, xv[j].w);
            const ulonglong2* wp = (const ulonglong2*)&s_w[c4*4 + j][mbase];
            ulonglong2 wA = wp[0], wB = wp[1];
            acc[0][0]=f2fma(wA.x,xd0,acc[0][0]); acc[0][1]=f2fma(wA.x,xd1,acc[0][1]);
            acc[0][2]=f2fma(wA.x,xd2,acc[0][2]); acc[0][3]=f2fma(wA.x,xd3,acc[0][3]);
            acc[1][0]=f2fma(wA.y,xd0,acc[1][0]); acc[1][1]=f2fma(wA.y,xd1,acc[1][1]);
            acc[1][2]=f2fma(wA.y,xd2,acc[1][2]); acc[1][3]=f2fma(wA.y,xd3,acc[1][3]);
            acc[2][0]=f2fma(wB.x,xd0,acc[2][0]); acc[2][1]=f2fma(wB.x,xd1,acc[2][1]);
            acc[2][2]=f2fma(wB.x,xd2,acc[2][2]); acc[2][3]=f2fma(wB.x,xd3,acc[2][3]);
            acc[3][0]=f2fma(wB.y,xd0,acc[3][0]); acc[3][1]=f2fma(wB.y,xd1,acc[3][1]);
            acc[3][2]=f2fma(wB.y,xd2,acc[3][2]); acc[3][3]=f2fma(wB.y,xd3,acc[3][3]);
        }
        if (c4 < 15) {
            #pragma unroll
            for (int j = 0; j < 4; j++) xv[j] = xn[j];
        }
    }

    float4 gv = *(const float4*)&g_gmap[(size_t)b*HWSZ + pix];
    float4 sv = *(const float4*)&g_smap[(size_t)b*HWSZ + pix];
    float gs[4] = {gv.x, gv.y, gv.z, gv.w};
    float ss[4] = {sv.x, sv.y, sv.z, sv.w};

    uint32_t* fh32 = (uint32_t*)g_fh;
    uint32_t* fl32 = (uint32_t*)g_fl;
    #pragma unroll
    for (int p = 0; p < 4; p++) {
        uint32_t H[4], L[4];
        #pragma unroll
        for (int mp = 0; mp < 4; mp++) {
            float alo, ahi;
            upk2(acc[mp][p], alo, ahi);
            float v0 = ss[p] * (gs[p]*alo + s_b[mbase + 2*mp    ]);
            float v1 = ss[p] * (gs[p]*ahi + s_b[mbase + 2*mp + 1]);
            H[mp] = packbf(v0, v1, L[mp]);
        }
        size_t gp = ((size_t)b*HWSZ + pix + p)*32 + (ms*16 + mg*4);
        *(uint4*)&fh32[gp] = make_uint4(H[0],H[1],H[2],H[3]);
        *(uint4*)&fl32[gp] = make_uint4(L[0],L[1],L[2],L[3]);
    }
}

// ---------------- K4: conv3x3<64> + fc + residual via bf16 mma.sync --------
__global__ __launch_bounds__(256)
void conv64fc_mma(const uint4* __restrict__ wf, const float* __restrict__ b2,
                  const uint4* __restrict__ fcf, const float* __restrict__ fcb,
                  const float* __restrict__ resid, float* __restrict__ out)
{
    __shared__ __align__(16) uint16_t s_buf[2*128*FPAD];
    __shared__ float s_b2[64], s_fcb[64];

    const int tid = threadIdx.x;
    const int wid = tid >> 5, lane = tid & 31;
    const int g = lane >> 2, t2 = (lane & 3) * 2;
    const int b  = blockIdx.z;
    const int w0 = blockIdx.x*32, h0 = blockIdx.y*4;

    if (tid < 64) { s_b2[tid] = b2[tid]; s_fcb[tid] = fcb[tid]; }

    uint16_t* s_hi = s_buf;
    uint16_t* s_lo = s_buf + 128*FPAD;

    const uint32_t* fh32 = (const uint32_t*)g_fh + (size_t)b*HWSZ*32;
    const uint32_t* fl32 = (const uint32_t*)g_fl + (size_t)b*HWSZ*32;

    const int m0 = wid*16 + g, m1 = m0 + 8;
    const int ph0 = m0 >> 5, pw0 = m0 & 31;
    const int ph1 = m1 >> 5, pw1 = m1 & 31;

    float d[8][4];
    #pragma unroll
    for (int nt = 0; nt < 8; nt++)
        #pragma unroll
        for (int i = 0; i < 4; i++) d[nt][i] = 0.f;

    for (int kh = 0; kh < 2; kh++) {
        if (kh) __syncthreads();
        #pragma unroll
        for (int it = 0; it < 4; it++) {
            int idx = tid + it*256;
            if (idx < 816) {
                int pos = idx >> 2, q = idx & 3;
                int h = pos/34, w = pos%34;
                int gh = h0 - 1 + h, gw = w0 - 1 + w;
                bool inb = (gh >= 0 && gh < HH && gw >= 0 && gw < WW);
                uint4 hv = make_uint4(0,0,0,0), lv = make_uint4(0,0,0,0);
                if (inb) {
                    size_t ga = ((size_t)(gh*WW + gw))*32 + kh*16 + q*4;
                    hv = *(const uint4*)&fh32[ga];
                    lv = *(const uint4*)&fl32[ga];
                }
                *(uint4*)&s_hi[pos*CPAD + q*8] = hv;
                *(uint4*)&s_lo[pos*CPAD + q*8] = lv;
            }
        }
        __syncthreads();

        for (int t = 0; t < 9; t++) {
            const int dr = t/3, dc = t%3;
            const int r0 = ((ph0 + dr)*34 + pw0 + dc)*CPAD;
            const int r1 = ((ph1 + dr)*34 + pw1 + dc)*CPAD;
            #pragma unroll
            for (int ks = 0; ks < 2; ks++) {
                uint4 bfr[8];
                const uint4* wp = wf + (size_t)(((t*2 + kh)*2 + ks)*8)*32 + lane;
                #pragma unroll
                for (int nt = 0; nt < 8; nt++) bfr[nt] = wp[nt*32];

                const int k = ks*16 + t2;
                uint32_t ah[4], al[4];
                ah[0] = *(const uint32_t*)&s_hi[r0 + k];
                ah[1] = *(const uint32_t*)&s_hi[r1 + k];
                ah[2] = *(const uint32_t*)&s_hi[r0 + k + 8];
                ah[3] = *(const uint32_t*)&s_hi[r1 + k + 8];
                al[0] = *(const uint32_t*)&s_lo[r0 + k];
                al[1] = *(const uint32_t*)&s_lo[r1 + k];
                al[2] = *(const uint32_t*)&s_lo[r0 + k + 8];
                al[3] = *(const uint32_t*)&s_lo[r1 + k + 8];

                #pragma unroll
                for (int nt = 0; nt < 8; nt++) {
                    mma_bf16(d[nt], ah, bfr[nt].x, bfr[nt].y);
                    mma_bf16(d[nt], al, bfr[nt].x, bfr[nt].y);
                    mma_bf16(d[nt], ah, bfr[nt].z, bfr[nt].w);
                }
            }
        }
    }
    __syncthreads();

    uint16_t* f_hi = s_buf;
    uint16_t* f_lo = s_buf + 128*FPAD;
    #pragma unroll
    for (int nt = 0; nt < 8; nt++) {
        int oc = nt*8 + t2;
        float b0v = s_b2[oc], b1v = s_b2[oc+1];
        float v00 = fmaxf(d[nt][0] + b0v, 0.f);
        float v01 = fmaxf(d[nt][1] + b1v, 0.f);
        float v10 = fmaxf(d[nt][2] + b0v, 0.f);
        float v11 = fmaxf(d[nt][3] + b1v, 0.f);
        uint32_t l0, l1;
        uint32_t h0v = packbf(v00, v01, l0);
        uint32_t h1v = packbf(v10, v11, l1);
        *(uint32_t*)&f_hi[m0*FPAD + oc] = h0v;
        *(uint32_t*)&f_hi[m1*FPAD + oc] = h1v;
        *(uint32_t*)&f_lo[m0*FPAD + oc] = l0;
        *(uint32_t*)&f_lo[m1*FPAD + oc] = l1;
    }
    __syncthreads();

    float e[8][4];
    #pragma unroll
    for (int nt = 0; nt < 8; nt++)
        #pragma unroll
        for (int i = 0; i < 4; i++) e[nt][i] = 0.f;

    #pragma unroll
    for (int ks = 0; ks < 4; ks++) {
        uint4 bfr[8];
        const uint4* wp = fcf + (ks*8)*32 + lane;
        #pragma unroll
        for (int nt = 0; nt < 8; nt++) bfr[nt] = wp[nt*32];

        const int k = ks*16 + t2;
        uint32_t ah[4], al[4];
        ah[0] = *(const uint32_t*)&f_hi[m0*FPAD + k];
        ah[1] = *(const uint32_t*)&f_hi[m1*FPAD + k];
        ah[2] = *(const uint32_t*)&f_hi[m0*FPAD + k + 8];
        ah[3] = *(const uint32_t*)&f_hi[m1*FPAD + k + 8];
        al[0] = *(const uint32_t*)&f_lo[m0*FPAD + k];
        al[1] = *(const uint32_t*)&f_lo[m1*FPAD + k];
        al[2] = *(const uint32_t*)&f_lo[m0*FPAD + k + 8];
        al[3] = *(const uint32_t*)&f_lo[m1*FPAD + k + 8];

        #pragma unroll
        for (int nt = 0; nt < 8; nt++) {
            mma_bf16(e[nt], ah, bfr[nt].x, bfr[nt].y);
            mma_bf16(e[nt], al, bfr[nt].x, bfr[nt].y);
            mma_bf16(e[nt], ah, bfr[nt].z, bfr[nt].w);
        }
    }

    const size_t base = (size_t)b*64*HWSZ;
    const int p0 = (h0 + ph0)*WW + w0 + pw0;
    const int p1 = (h0 + ph1)*WW + w0 + pw1;
    #pragma unroll
    for (int nt = 0; nt < 8; nt++) {
        int oc = nt*8 + t2;
        size_t i00 = base + (size_t)oc*HWSZ + p0;
        size_t i01 = i00 + HWSZ;
        size_t i10 = base + (size_t)oc*HWSZ + p1;
        size_t i11 = i10 + HWSZ;
        out[i00] = e[nt][0] + s_fcb[oc]   + resid[i00];
        out[i01] = e[nt][1] + s_fcb[oc+1] + resid[i01];
        out[i10] = e[nt][2] + s_fcb[oc]   + resid[i10];
        out[i11] = e[nt][3] + s_fcb[oc+1] + resid[i11];
    }
}

// ---------------------------------------------------------------------------
extern "C" void kernel_launch(void* const* d_in, const int* in_sizes, int n_in,
                              void* d_out, int out_size)
{
    (void)in_sizes; (void)n_in; (void)out_size;
    const float* x     = (const float*)d_in[0];
    const float* ba_w1 = (const float*)d_in[1];
    const float* ba_b1 = (const float*)d_in[2];
    const float* ba_w2 = (const float*)d_in[3];
    const float* ba_b2 = (const float*)d_in[4];
    // d_in[5..12]: offset branch — dead code in the reference, skipped.
    const float* rk5w  = (const float*)d_in[13];
    const float* rk5b  = (const float*)d_in[14];
    const float* rk7w  = (const float*)d_in[15];
    const float* rk7b  = (const float*)d_in[16];
    const float* lk5w  = (const float*)d_in[17];
    const float* lk5b  = (const float*)d_in[18];
    const float* lk7w  = (const float*)d_in[19];
    const float* lk7b  = (const float*)d_in[20];
    const float* sfw   = (const float*)d_in[21];
    const float* sfb   = (const float*)d_in[22];
    const float* sfg   = (const float*)d_in[23];
    const float* sfbb  = (const float*)d_in[24];
    const float* sfm   = (const float*)d_in[25];
    const float* sfv   = (const float*)d_in[26];
    const float* fcw   = (const float*)d_in[27];
    const float* fcb   = (const float*)d_in[28];
    float* out = (float*)d_out;

    float *pWeff, *pBeff, *pB2;
    uint4 *pWf, *pFcf, *pWf1;
    cudaGetSymbolAddress((void**)&pWeff, g_Weff);
    cudaGetSymbolAddress((void**)&pBeff, g_beff);
    cudaGetSymbolAddress((void**)&pB2,   g_b2);
    cudaGetSymbolAddress((void**)&pWf,   g_wf);
    cudaGetSymbolAddress((void**)&pFcf,  g_fcf);
    cudaGetSymbolAddress((void**)&pWf1,  g_wf1);

    build_weff<<<16, 256>>>(rk5w, rk5b, rk7w, rk7b, lk5w, lk5b, lk7w, lk7b);
    prep_b<<<1, 64>>>(sfb, sfg, sfbb, sfm, sfv);
    prep_frag<<<58, 256>>>(sfw, sfg, sfv, fcw, ba_w1);
    xpose_k<<<dim3(HWSZ/128, BB), 256>>>(x);

    conv32_edge_mma<<<dim3(WW/32, HH/4, BB), 256>>>(pWf1, ba_b1, ba_w2, ba_b2);
    fusion_k<<<dim3(HWSZ/256, 2, BB), 256>>>(x, pWeff, pBeff);
    conv64fc_mma<<<dim3(WW/32, HH/4, BB), 256>>>(pWf, pB2, pFcf, fcb, x, out);
}

// round 16
// speedup vs baseline: 1.5403x; 1.1450x over previous
#include <cuda_runtime.h>
#include <cuda_bf16.h>
#include <cstdint>
#include <cstddef>

#define BB 4
#define HH 160
#define WW 160
#define HWSZ (HH*WW)
#define CPAD 40          // padded channel stride (u16) for conv staging
#define FPAD 72          // padded k stride (u16) for fc/fusion phase
#define XPXS 33          // u32 stride per pixel in transpose smem

typedef unsigned long long ull;

// ---------------- bf16 mma.sync helpers ------------------------------------
__device__ __forceinline__ void mma_bf16(float d[4], const uint32_t a[4],
                                         uint32_t b0, uint32_t b1) {
    asm volatile(
        "mma.sync.aligned.m16n8k16.row.col.f32.bf16.bf16.f32 "
        "{%0,%1,%2,%3}, {%4,%5,%6,%7}, {%8,%9}, {%0,%1,%2,%3};"
        : "+f"(d[0]), "+f"(d[1]), "+f"(d[2]), "+f"(d[3])
        : "r"(a[0]), "r"(a[1]), "r"(a[2]), "r"(a[3]), "r"(b0), "r"(b1));
}
__device__ __forceinline__ uint32_t bfpack2(float x, float y) {
    __nv_bfloat162 h = __halves2bfloat162(__float2bfloat16(x), __float2bfloat16(y));
    return *(uint32_t*)&h;
}
__device__ __forceinline__ float bfunp_lo(uint32_t v) {
    __nv_bfloat162 h = *(__nv_bfloat162*)&v;
    return __bfloat162float(__low2bfloat16(h));
}
__device__ __forceinline__ float bfunp_hi(uint32_t v) {
    __nv_bfloat162 h = *(__nv_bfloat162*)&v;
    return __bfloat162float(__high2bfloat16(h));
}
__device__ __forceinline__ uint32_t packbf(float v0, float v1, uint32_t& lo) {
    __nv_bfloat16 h0 = __float2bfloat16(v0);
    __nv_bfloat16 h1 = __float2bfloat16(v1);
    lo = bfpack2(v0 - __bfloat162float(h0), v1 - __bfloat162float(h1));
    return (uint32_t)(*(uint16_t*)&h0) | ((uint32_t)(*(uint16_t*)&h1) << 16);
}

// ---------------- scratch (device globals; no allocation allowed) ----------
__device__ __align__(128) float g_gmap[BB*HWSZ];
__device__ __align__(128) float g_smap[BB*HWSZ];
__device__ __align__(128) float g_Weff[64*64];
__device__ __align__(128) float g_beff[64];
__device__ __align__(128) float g_b2[64];
__device__ __align__(128) uint4 g_wf[9216];       // conv64 frags
__device__ __align__(128) uint4 g_fcf[1024];      // fc frags
__device__ __align__(128) uint4 g_wf1[4608];      // conv32 frags
__device__ __align__(128) uint4 g_wff[1024];      // Weff (fusion) frags
__device__ __align__(128) uint16_t g_xh[(size_t)BB*HWSZ*64];  // x bf16 hi, ch-last
__device__ __align__(128) uint16_t g_xl[(size_t)BB*HWSZ*64];  // x bf16 lo
__device__ __align__(128) uint16_t g_fh[(size_t)BB*HWSZ*64];  // fusion hi, ch-last
__device__ __align__(128) uint16_t g_fl[(size_t)BB*HWSZ*64];  // fusion lo

// ---------------- K0a: effective dyn1d weights (sum over K) ----------------
__global__ void build_weff(const float* __restrict__ rk5w, const float* __restrict__ rk5b,
                           const float* __restrict__ rk7w, const float* __restrict__ rk7b,
                           const float* __restrict__ lk5w, const float* __restrict__ lk5b,
                           const float* __restrict__ lk7w, const float* __restrict__ lk7b)
{
    int id = blockIdx.x*blockDim.x + threadIdx.x;
    if (id >= 64*64) return;
    int m = id >> 6, c = id & 63;
    const float* w; const float* bs; int K, o;
    if      (m < 16) { w = rk5w; bs = rk5b; K = 5; o = m;    }
    else if (m < 32) { w = rk7w; bs = rk7b; K = 7; o = m-16; }
    else if (m < 48) { w = lk5w; bs = lk5b; K = 5; o = m-32; }
    else             { w = lk7w; bs = lk7b; K = 7; o = m-48; }
    float acc = 0.f;
    for (int k = 0; k < K; k++) acc += w[(o*K + k)*64 + c];
    g_Weff[m*64 + c] = acc;
    if (c == 0) {
        float bacc = 0.f;
        for (int k = 0; k < K; k++) bacc += bs[o*K + k];
        g_beff[m] = bacc;
    }
}

// ---------------- K0a2: pack Weff B-fragments (runs after build_weff) ------
__global__ void prep_wff()
{
    int id = blockIdx.x*blockDim.x + threadIdx.x;
    if (id >= 1024) return;
    int lane = id & 31; int rem = id >> 5;
    int nt = rem & 7; int ks = rem >> 3;
    int n  = nt*8 + (lane >> 2);
    int k0 = ks*16 + (lane & 3)*2;
    uint4 rec;
    rec.x = packbf(g_Weff[n*64 + k0    ], g_Weff[n*64 + k0 + 1], rec.z);
    rec.y = packbf(g_Weff[n*64 + k0 + 8], g_Weff[n*64 + k0 + 9], rec.w);
    g_wff[id] = rec;
}

// ---------------- K0b: BN-folded bias for conv64 ---------------------------
__global__ void prep_b(const float* __restrict__ b2s, const float* __restrict__ bg,
                       const float* __restrict__ bbta, const float* __restrict__ bm,
                       const float* __restrict__ bv)
{
    int id = blockIdx.x*blockDim.x + threadIdx.x;
    if (id < 64) {
        float scc = bg[id] * rsqrtf(bv[id] + 1e-5f);
        g_b2[id] = b2s[id]*scc + bbta[id] - bm[id]*scc;
    }
}

// ---------------- K0c: pack mma B-fragments (hi/lo split) ------------------
__global__ void prep_frag(const float* __restrict__ sfw, const float* __restrict__ bg,
                          const float* __restrict__ bv, const float* __restrict__ fcw,
                          const float* __restrict__ w1)
{
    int id = blockIdx.x*blockDim.x + threadIdx.x;
    if (id < 9216) {
        int lane = id & 31; int rem = id >> 5;
        int nt = rem & 7; rem >>= 3;
        int ks = rem & 1; rem >>= 1;
        int kh = rem & 1; int t = rem >> 1;
        int n  = nt*8 + (lane >> 2);
        int k0 = kh*32 + ks*16 + (lane & 3)*2;
        float sc = bg[n] * rsqrtf(bv[n] + 1e-5f);
        float w00 = sfw[(n*64 + k0    )*9 + t] * sc;
        float w01 = sfw[(n*64 + k0 + 1)*9 + t] * sc;
        float w08 = sfw[(n*64 + k0 + 8)*9 + t] * sc;
        float w09 = sfw[(n*64 + k0 + 9)*9 + t] * sc;
        uint4 rec;
        rec.x = packbf(w00, w01, rec.z);
        rec.y = packbf(w08, w09, rec.w);
        g_wf[id] = rec;
    } else if (id < 10240) {
        int fid = id - 9216;
        int lane = fid & 31; int rem = fid >> 5;
        int nt = rem & 7; int ks = rem >> 3;
        int n  = nt*8 + (lane >> 2);
        int k0 = ks*16 + (lane & 3)*2;
        uint4 rec;
        rec.x = packbf(fcw[n*64 + k0    ], fcw[n*64 + k0 + 1], rec.z);
        rec.y = packbf(fcw[n*64 + k0 + 8], fcw[n*64 + k0 + 9], rec.w);
        g_fcf[fid] = rec;
    } else if (id < 14848) {
        int fid = id - 10240;
        int lane = fid & 31; int rem = fid >> 5;
        int nt = rem & 3; rem >>= 2;
        int ks = rem & 1; rem >>= 1;
        int kh = rem & 1; int t = rem >> 1;
        int n  = nt*8 + (lane >> 2);
        int k0 = kh*32 + ks*16 + (lane & 3)*2;
        uint4 rec;
        rec.x = packbf(w1[(n*64 + k0    )*9 + t], w1[(n*64 + k0 + 1)*9 + t], rec.z);
        rec.y = packbf(w1[(n*64 + k0 + 8)*9 + t], w1[(n*64 + k0 + 9)*9 + t], rec.w);
        g_wf1[fid] = rec;
    }
}

// ---------------- K0d: transpose x -> channel-last bf16 hi/lo --------------
__global__ __launch_bounds__(256)
void xpose_k(const float* __restrict__ x)
{
    __shared__ uint32_t s_h[128*XPXS];
    __shared__ uint32_t s_l[128*XPXS];
    const int tid = threadIdx.x;
    const int b   = blockIdx.y;
    const int px0 = blockIdx.x*128;
    const int px  = tid & 127;
    const int hf  = tid >> 7;

    #pragma unroll
    for (int c2 = 0; c2 < 16; c2++) {
        int c = hf*32 + c2*2;
        const float* fp = x + ((size_t)(b*64 + c))*HWSZ + px0 + px;
        float v0 = fp[0];
        float v1 = fp[HWSZ];
        uint32_t lw;
        uint32_t hw = packbf(v0, v1, lw);
        s_h[px*XPXS + hf*16 + c2] = hw;
        s_l[px*XPXS + hf*16 + c2] = lw;
    }
    __syncthreads();

    uint32_t* xh32 = (uint32_t*)g_xh;
    uint32_t* xl32 = (uint32_t*)g_xl;
    #pragma unroll
    for (int k = 0; k < 4; k++) {
        int idx = tid + k*256;
        int p = idx >> 3, q = idx & 7;
        size_t ga = ((size_t)b*HWSZ + px0 + p)*32 + q*4;
        uint4 hv, lv;
        hv.x = s_h[p*XPXS + q*4    ]; hv.y = s_h[p*XPXS + q*4 + 1];
        hv.z = s_h[p*XPXS + q*4 + 2]; hv.w = s_h[p*XPXS + q*4 + 3];
        lv.x = s_l[p*XPXS + q*4    ]; lv.y = s_l[p*XPXS + q*4 + 1];
        lv.z = s_l[p*XPXS + q*4 + 2]; lv.w = s_l[p*XPXS + q*4 + 3];
        *(uint4*)&xh32[ga] = hv;
        *(uint4*)&xl32[ga] = lv;
    }
}

// ---------------- K1: conv3x3<32> + sobel edge + attention via mma.sync ----
__global__ __launch_bounds__(256)
void conv32_edge_mma(const uint4* __restrict__ wf1, const float* __restrict__ b1,
                     const float* __restrict__ baw2, const float* __restrict__ bab2)
{
    __shared__ __align__(16) uint16_t s_hi[204*CPAD];
    __shared__ __align__(16) uint16_t s_lo[204*CPAD];
    __shared__ float s_ep[2][128], s_sp[2][128];
    __shared__ float s_b1[32], s_w2[32];

    const int tid = threadIdx.x;
    const int wid = tid >> 5, lane = tid & 31;
    const int g = lane >> 2, t2 = (lane & 3) * 2;
    const int b  = blockIdx.z;
    const int w0 = blockIdx.x*32, h0 = blockIdx.y*4;

    if (tid < 32) { s_b1[tid] = b1[tid]; s_w2[tid] = baw2[tid]; }

    const int m0 = wid*16 + g, m1 = m0 + 8;
    const int ph0 = m0 >> 5, pw0 = m0 & 31;
    const int ph1 = m1 >> 5, pw1 = m1 & 31;

    const int ep  = tid & 127;
    const int cig = tid >> 7;
    const int eph = ep >> 5, epw = ep & 31;

    const uint32_t* xh32 = (const uint32_t*)g_xh + (size_t)b*HWSZ*32;
    const uint32_t* xl32 = (const uint32_t*)g_xl + (size_t)b*HWSZ*32;

    float d[4][4];
    #pragma unroll
    for (int nt = 0; nt < 4; nt++)
        #pragma unroll
        for (int i = 0; i < 4; i++) d[nt][i] = 0.f;
    float edge_acc = 0.f, sum_acc = 0.f;

    for (int kh = 0; kh < 2; kh++) {
        if (kh) __syncthreads();
        #pragma unroll
        for (int it = 0; it < 4; it++) {
            int idx = tid + it*256;
            if (idx < 816) {
                int pos = idx >> 2, q = idx & 3;
                int h = pos/34, w = pos%34;
                int gh = h0 - 1 + h, gw = w0 - 1 + w;
                bool inb = (gh >= 0 && gh < HH && gw >= 0 && gw < WW);
                uint4 hv = make_uint4(0,0,0,0), lv = make_uint4(0,0,0,0);
                if (inb) {
                    size_t ga = ((size_t)(gh*WW + gw))*32 + kh*16 + q*4;
                    hv = *(const uint4*)&xh32[ga];
                    lv = *(const uint4*)&xl32[ga];
                }
                *(uint4*)&s_hi[pos*CPAD + q*8] = hv;
                *(uint4*)&s_lo[pos*CPAD + q*8] = lv;
            }
        }
        __syncthreads();

        // ---- edge (hi-only) + channel-sum (hi+lo) partials ----
        {
            float v[7][16];
            const int base_h = eph, base_w = epw;
            #pragma unroll
            for (int ppos = 0; ppos < 7; ppos++) {
                int dh, dw;
                if (ppos < 6) {
                    if (kh == 0) { dh = ppos >> 1; dw = (ppos & 1) * 2; }
                    else         { dh = (ppos & 1) * 2; dw = ppos >> 1; }
                } else { dh = 1; dw = 1; }
                int hw = (base_h + dh)*34 + (base_w + dw);
                const uint4* ph_ = (const uint4*)&s_hi[hw*CPAD + cig*16];
                #pragma unroll
                for (int q = 0; q < 2; q++) {
                    uint4 hv = ph_[q];
                    const uint32_t hw_[4] = {hv.x, hv.y, hv.z, hv.w};
                    #pragma unroll
                    for (int r = 0; r < 4; r++) {
                        v[ppos][q*8 + r*2    ] = bfunp_lo(hw_[r]);
                        v[ppos][q*8 + r*2 + 1] = bfunp_hi(hw_[r]);
                    }
                }
                if (ppos == 6) {
                    const uint4* pl_ = (const uint4*)&s_lo[hw*CPAD + cig*16];
                    #pragma unroll
                    for (int q = 0; q < 2; q++) {
                        uint4 lv = pl_[q];
                        const uint32_t lw_[4] = {lv.x, lv.y, lv.z, lv.w};
                        #pragma unroll
                        for (int r = 0; r < 4; r++) {
                            v[6][q*8 + r*2    ] += bfunp_lo(lw_[r]);
                            v[6][q*8 + r*2 + 1] += bfunp_hi(lw_[r]);
                        }
                    }
                }
            }
            float e = 0.f, s = 0.f;
            #pragma unroll
            for (int c = 0; c < 16; c++) {
                s += v[6][c];
                float gsum = (v[1][c] - v[0][c]) + 2.f*(v[3][c] - v[2][c]) + (v[5][c] - v[4][c]);
                e += fabsf(gsum);
            }
            edge_acc += e;
            sum_acc  += s;
        }

        // ---- conv MMAs: (ah+al)*bh ----
        for (int t = 0; t < 9; t++) {
            const int dr = t/3, dc = t%3;
            const int r0 = ((ph0 + dr)*34 + pw0 + dc)*CPAD;
            const int r1 = ((ph1 + dr)*34 + pw1 + dc)*CPAD;
            #pragma unroll
            for (int ks = 0; ks < 2; ks++) {
                uint2 bfr[4];
                const uint2* wp = (const uint2*)(wf1 + (size_t)(((t*2 + kh)*2 + ks)*4)*32 + lane);
                #pragma unroll
                for (int nt = 0; nt < 4; nt++) bfr[nt] = wp[nt*64];

                const int k = ks*16 + t2;
                uint32_t ah[4], al[4];
                ah[0] = *(const uint32_t*)&s_hi[r0 + k];
                ah[1] = *(const uint32_t*)&s_hi[r1 + k];
                ah[2] = *(const uint32_t*)&s_hi[r0 + k + 8];
                ah[3] = *(const uint32_t*)&s_hi[r1 + k + 8];
                al[0] = *(const uint32_t*)&s_lo[r0 + k];
                al[1] = *(const uint32_t*)&s_lo[r1 + k];
                al[2] = *(const uint32_t*)&s_lo[r0 + k + 8];
                al[3] = *(const uint32_t*)&s_lo[r1 + k + 8];

                #pragma unroll
                for (int nt = 0; nt < 4; nt++) {
                    mma_bf16(d[nt], ah, bfr[nt].x, bfr[nt].y);
                    mma_bf16(d[nt], al, bfr[nt].x, bfr[nt].y);
                }
            }
        }
    }

    s_ep[cig][ep] = edge_acc;
    s_sp[cig][ep] = sum_acc;

    float att0 = 0.f, att1 = 0.f;
    #pragma unroll
    for (int nt = 0; nt < 4; nt++) {
        int oc = nt*8 + t2;
        float b0v = s_b1[oc], b1v = s_b1[oc+1];
        float w0v = s_w2[oc], w1v = s_w2[oc+1];
        att0 += w0v*fmaxf(d[nt][0] + b0v, 0.f) + w1v*fmaxf(d[nt][1] + b1v, 0.f);
        att1 += w0v*fmaxf(d[nt][2] + b0v, 0.f) + w1v*fmaxf(d[nt][3] + b1v, 0.f);
    }
    att0 += __shfl_xor_sync(0xFFFFFFFF, att0, 1);
    att0 += __shfl_xor_sync(0xFFFFFFFF, att0, 2);
    att1 += __shfl_xor_sync(0xFFFFFFFF, att1, 1);
    att1 += __shfl_xor_sync(0xFFFFFFFF, att1, 2);
    __syncthreads();

    if ((lane & 3) == 0) {
        float bb = bab2[0];
        #pragma unroll
        for (int r = 0; r < 2; r++) {
            int m = r ? m1 : m0;
            float att = (r ? att1 : att0) + bb;
            float ed = (s_ep[0][m] + s_ep[1][m]) * (1.f/32.f);
            float sx =  s_sp[0][m] + s_sp[1][m];
            float z = att + ed;
            float a = 1.f / (1.f + expf(-z));
            float gv = 1.f + a;
            int mh = m >> 5, mw = m & 31;
            size_t pix = (size_t)b*HWSZ + (size_t)(h0 + mh)*WW + (w0 + mw);
            g_gmap[pix] = gv;
            g_smap[pix] = gv * sx;
        }
    }
}

// ---------------- K3: fusion GEMM via bf16 mma.sync ------------------------
// Block = 128 linear pixels. A = x channel-last hi/lo (staged coalesced,
// FPAD layout, conflict-free). 96 MMAs/warp. Epilogue: s*(g*acc + beff),
// written channel-last bf16 hi/lo.
__global__ __launch_bounds__(256)
void fusion_mma()
{
    __shared__ __align__(16) uint16_t s_buf[2*128*FPAD];
    __shared__ float s_be[64];

    const int tid = threadIdx.x;
    const int wid = tid >> 5, lane = tid & 31;
    const int g = lane >> 2, t2 = (lane & 3) * 2;
    const int b   = blockIdx.y;
    const int px0 = blockIdx.x*128;

    if (tid < 64) s_be[tid] = g_beff[tid];

    uint16_t* s_hi = s_buf;
    uint16_t* s_lo = s_buf + 128*FPAD;

    const uint32_t* xh32 = (const uint32_t*)g_xh + ((size_t)b*HWSZ + px0)*32;
    const uint32_t* xl32 = (const uint32_t*)g_xl + ((size_t)b*HWSZ + px0)*32;

    // stage 128 px x 64 ch, both planes (coalesced uint4)
    #pragma unroll
    for (int it = 0; it < 4; it++) {
        int idx = tid + it*256;
        int p = idx >> 3, q = idx & 7;
        uint4 hv = *(const uint4*)&xh32[(size_t)p*32 + q*4];
        uint4 lv = *(const uint4*)&xl32[(size_t)p*32 + q*4];
        *(uint4*)&s_hi[p*FPAD + q*8] = hv;
        *(uint4*)&s_lo[p*FPAD + q*8] = lv;
    }
    __syncthreads();

    const int m0 = wid*16 + g, m1 = m0 + 8;

    float d[8][4];
    #pragma unroll
    for (int nt = 0; nt < 8; nt++)
        #pragma unroll
        for (int i = 0; i < 4; i++) d[nt][i] = 0.f;

    #pragma unroll
    for (int ks = 0; ks < 4; ks++) {
        uint4 bfr[8];
        const uint4* wp = g_wff + (ks*8)*32 + lane;
        #pragma unroll
        for (int nt = 0; nt < 8; nt++) bfr[nt] = wp[nt*32];

        const int k = ks*16 + t2;
        uint32_t ah[4], al[4];
        ah[0] = *(const uint32_t*)&s_hi[m0*FPAD + k];
        ah[1] = *(const uint32_t*)&s_hi[m1*FPAD + k];
        ah[2] = *(const uint32_t*)&s_hi[m0*FPAD + k + 8];
        ah[3] = *(const uint32_t*)&s_hi[m1*FPAD + k + 8];
        al[0] = *(const uint32_t*)&s_lo[m0*FPAD + k];
        al[1] = *(const uint32_t*)&s_lo[m1*FPAD + k];
        al[2] = *(const uint32_t*)&s_lo[m0*FPAD + k + 8];
        al[3] = *(const uint32_t*)&s_lo[m1*FPAD + k + 8];

        #pragma unroll
        for (int nt = 0; nt < 8; nt++) {
            mma_bf16(d[nt], ah, bfr[nt].x, bfr[nt].y);
            mma_bf16(d[nt], al, bfr[nt].x, bfr[nt].y);
            mma_bf16(d[nt], ah, bfr[nt].z, bfr[nt].w);
        }
    }

    const float g0 = g_gmap[(size_t)b*HWSZ + px0 + m0];
    const float s0 = g_smap[(size_t)b*HWSZ + px0 + m0];
    const float g1 = g_gmap[(size_t)b*HWSZ + px0 + m1];
    const float s1 = g_smap[(size_t)b*HWSZ + px0 + m1];

    uint32_t* fh32 = (uint32_t*)g_fh + ((size_t)b*HWSZ + px0)*32;
    uint32_t* fl32 = (uint32_t*)g_fl + ((size_t)b*HWSZ + px0)*32;
    #pragma unroll
    for (int nt = 0; nt < 8; nt++) {
        int ch = nt*8 + t2;
        float be0 = s_be[ch], be1 = s_be[ch+1];
        uint32_t l0, l1;
        uint32_t h0v = packbf(s0*(g0*d[nt][0] + be0), s0*(g0*d[nt][1] + be1), l0);
        uint32_t h1v = packbf(s1*(g1*d[nt][2] + be0), s1*(g1*d[nt][3] + be1), l1);
        fh32[(size_t)m0*32 + (ch >> 1)] = h0v;
        fl32[(size_t)m0*32 + (ch >> 1)] = l0;
        fh32[(size_t)m1*32 + (ch >> 1)] = h1v;
        fl32[(size_t)m1*32 + (ch >> 1)] = l1;
    }
}

// ---------------- K4: conv3x3<64> + fc + residual via bf16 mma.sync --------
__global__ __launch_bounds__(256)
void conv64fc_mma(const uint4* __restrict__ wf, const float* __restrict__ b2,
                  const uint4* __restrict__ fcf, const float* __restrict__ fcb,
                  const float* __restrict__ resid, float* __restrict__ out)
{
    __shared__ __align__(16) uint16_t s_buf[2*128*FPAD];
    __shared__ float s_b2[64], s_fcb[64];

    const int tid = threadIdx.x;
    const int wid = tid >> 5, lane = tid & 31;
    const int g = lane >> 2, t2 = (lane & 3) * 2;
    const int b  = blockIdx.z;
    const int w0 = blockIdx.x*32, h0 = blockIdx.y*4;

    if (tid < 64) { s_b2[tid] = b2[tid]; s_fcb[tid] = fcb[tid]; }

    uint16_t* s_hi = s_buf;
    uint16_t* s_lo = s_buf + 128*FPAD;

    const uint32_t* fh32 = (const uint32_t*)g_fh + (size_t)b*HWSZ*32;
    const uint32_t* fl32 = (const uint32_t*)g_fl + (size_t)b*HWSZ*32;

    const int m0 = wid*16 + g, m1 = m0 + 8;
    const int ph0 = m0 >> 5, pw0 = m0 & 31;
    const int ph1 = m1 >> 5, pw1 = m1 & 31;

    float d[8][4];
    #pragma unroll
    for (int nt = 0; nt < 8; nt++)
        #pragma unroll
        for (int i = 0; i < 4; i++) d[nt][i] = 0.f;

    for (int kh = 0; kh < 2; kh++) {
        if (kh) __syncthreads();
        #pragma unroll
        for (int it = 0; it < 4; it++) {
            int idx = tid + it*256;
            if (idx < 816) {
                int pos = idx >> 2, q = idx & 3;
                int h = pos/34, w = pos%34;
                int gh = h0 - 1 + h, gw = w0 - 1 + w;
                bool inb = (gh >= 0 && gh < HH && gw >= 0 && gw < WW);
                uint4 hv = make_uint4(0,0,0,0), lv = make_uint4(0,0,0,0);
                if (inb) {
                    size_t ga = ((size_t)(gh*WW + gw))*32 + kh*16 + q*4;
                    hv = *(const uint4*)&fh32[ga];
                    lv = *(const uint4*)&fl32[ga];
                }
                *(uint4*)&s_hi[pos*CPAD + q*8] = hv;
                *(uint4*)&s_lo[pos*CPAD + q*8] = lv;
            }
        }
        __syncthreads();

        for (int t = 0; t < 9; t++) {
            const int dr = t/3, dc = t%3;
            const int r0 = ((ph0 + dr)*34 + pw0 + dc)*CPAD;
            const int r1 = ((ph1 + dr)*34 + pw1 + dc)*CPAD;
            #pragma unroll
            for (int ks = 0; ks < 2; ks++) {
                uint4 bfr[8];
                const uint4* wp = wf + (size_t)(((t*2 + kh)*2 + ks)*8)*32 + lane;
                #pragma unroll
                for (int nt = 0; nt < 8; nt++) bfr[nt] = wp[nt*32];

                const int k = ks*16 + t2;
                uint32_t ah[4], al[4];
                ah[0] = *(const uint32_t*)&s_hi[r0 + k];
                ah[1] = *(const uint32_t*)&s_hi[r1 + k];
                ah[2] = *(const uint32_t*)&s_hi[r0 + k + 8];
                ah[3] = *(const uint32_t*)&s_hi[r1 + k + 8];
                al[0] = *(const uint32_t*)&s_lo[r0 + k];
                al[1] = *(const uint32_t*)&s_lo[r1 + k];
                al[2] = *(const uint32_t*)&s_lo[r0 + k + 8];
                al[3] = *(const uint32_t*)&s_lo[r1 + k + 8];

                #pragma unroll
                for (int nt = 0; nt < 8; nt++) {
                    mma_bf16(d[nt], ah, bfr[nt].x, bfr[nt].y);
                    mma_bf16(d[nt], al, bfr[nt].x, bfr[nt].y);
                    mma_bf16(d[nt], ah, bfr[nt].z, bfr[nt].w);
                }
            }
        }
    }
    __syncthreads();

    uint16_t* f_hi = s_buf;
    uint16_t* f_lo = s_buf + 128*FPAD;
    #pragma unroll
    for (int nt = 0; nt < 8; nt++) {
        int oc = nt*8 + t2;
        float b0v = s_b2[oc], b1v = s_b2[oc+1];
        float v00 = fmaxf(d[nt][0] + b0v, 0.f);
        float v01 = fmaxf(d[nt][1] + b1v, 0.f);
        float v10 = fmaxf(d[nt][2] + b0v, 0.f);
        float v11 = fmaxf(d[nt][3] + b1v, 0.f);
        uint32_t l0, l1;
        uint32_t h0v = packbf(v00, v01, l0);
        uint32_t h1v = packbf(v10, v11, l1);
        *(uint32_t*)&f_hi[m0*FPAD + oc] = h0v;
        *(uint32_t*)&f_hi[m1*FPAD + oc] = h1v;
        *(uint32_t*)&f_lo[m0*FPAD + oc] = l0;
        *(uint32_t*)&f_lo[m1*FPAD + oc] = l1;
    }
    __syncthreads();

    float e[8][4];
    #pragma unroll
    for (int nt = 0; nt < 8; nt++)
        #pragma unroll
        for (int i = 0; i < 4; i++) e[nt][i] = 0.f;

    #pragma unroll
    for (int ks = 0; ks < 4; ks++) {
        uint4 bfr[8];
        const uint4* wp = fcf + (ks*8)*32 + lane;
        #pragma unroll
        for (int nt = 0; nt < 8; nt++) bfr[nt] = wp[nt*32];

        const int k = ks*16 + t2;
        uint32_t ah[4], al[4];
        ah[0] = *(const uint32_t*)&f_hi[m0*FPAD + k];
        ah[1] = *(const uint32_t*)&f_hi[m1*FPAD + k];
        ah[2] = *(const uint32_t*)&f_hi[m0*FPAD + k + 8];
        ah[3] = *(const uint32_t*)&f_hi[m1*FPAD + k + 8];
        al[0] = *(const uint32_t*)&f_lo[m0*FPAD + k];
        al[1] = *(const uint32_t*)&f_lo[m1*FPAD + k];
        al[2] = *(const uint32_t*)&f_lo[m0*FPAD + k + 8];
        al[3] = *(const uint32_t*)&f_lo[m1*FPAD + k + 8];

        #pragma unroll
        for (int nt = 0; nt < 8; nt++) {
            mma_bf16(e[nt], ah, bfr[nt].x, bfr[nt].y);
            mma_bf16(e[nt], al, bfr[nt].x, bfr[nt].y);
            mma_bf16(e[nt], ah, bfr[nt].z, bfr[nt].w);
        }
    }

    const size_t base = (size_t)b*64*HWSZ;
    const int p0 = (h0 + ph0)*WW + w0 + pw0;
    const int p1 = (h0 + ph1)*WW + w0 + pw1;
    #pragma unroll
    for (int nt = 0; nt < 8; nt++) {
        int oc = nt*8 + t2;
        size_t i00 = base + (size_t)oc*HWSZ + p0;
        size_t i01 = i00 + HWSZ;
        size_t i10 = base + (size_t)oc*HWSZ + p1;
        size_t i11 = i10 + HWSZ;
        out[i00] = e[nt][0] + s_fcb[oc]   + resid[i00];
        out[i01] = e[nt][1] + s_fcb[oc+1] + resid[i01];
        out[i10] = e[nt][2] + s_fcb[oc]   + resid[i10];
        out[i11] = e[nt][3] + s_fcb[oc+1] + resid[i11];
    }
}

// ---------------------------------------------------------------------------
extern "C" void kernel_launch(void* const* d_in, const int* in_sizes, int n_in,
                              void* d_out, int out_size)
{
    (void)in_sizes; (void)n_in; (void)out_size;
    const float* x     = (const float*)d_in[0];
    const float* ba_w1 = (const float*)d_in[1];
    const float* ba_b1 = (const float*)d_in[2];
    const float* ba_w2 = (const float*)d_in[3];
    const float* ba_b2 = (const float*)d_in[4];
    // d_in[5..12]: offset branch — dead code in the reference, skipped.
    const float* rk5w  = (const float*)d_in[13];
    const float* rk5b  = (const float*)d_in[14];
    const float* rk7w  = (const float*)d_in[15];
    const float* rk7b  = (const float*)d_in[16];
    const float* lk5w  = (const float*)d_in[17];
    const float* lk5b  = (const float*)d_in[18];
    const float* lk7w  = (const float*)d_in[19];
    const float* lk7b  = (const float*)d_in[20];
    const float* sfw   = (const float*)d_in[21];
    const float* sfb   = (const float*)d_in[22];
    const float* sfg   = (const float*)d_in[23];
    const float* sfbb  = (const float*)d_in[24];
    const float* sfm   = (const float*)d_in[25];
    const float* sfv   = (const float*)d_in[26];
    const float* fcw   = (const float*)d_in[27];
    const float* fcb   = (const float*)d_in[28];
    float* out = (float*)d_out;

    float *pB2;
    uint4 *pWf, *pFcf, *pWf1;
    cudaGetSymbolAddress((void**)&pB2,   g_b2);
    cudaGetSymbolAddress((void**)&pWf,   g_wf);
    cudaGetSymbolAddress((void**)&pFcf,  g_fcf);
    cudaGetSymbolAddress((void**)&pWf1,  g_wf1);

    build_weff<<<16, 256>>>(rk5w, rk5b, rk7w, rk7b, lk5w, lk5b, lk7w, lk7b);
    prep_wff<<<4, 256>>>();
    prep_b<<<1, 64>>>(sfb, sfg, sfbb, sfm, sfv);
    prep_frag<<<58, 256>>>(sfw, sfg, sfv, fcw, ba_w1);
    xpose_k<<<dim3(HWSZ/128, BB), 256>>>(x);

    conv32_edge_mma<<<dim3(WW/32, HH/4, BB), 256>>>(pWf1, ba_b1, ba_w2, ba_b2);
    fusion_mma<<<dim3(HWSZ/128, BB), 256>>>();
    conv64fc_mma<<<dim3(WW/32, HH/4, BB), 256>>>(pWf, pB2, pFcf, fcb, x, out);
}

// round 17
// speedup vs baseline: 1.5891x; 1.0317x over previous
#include <cuda_runtime.h>
#include <cuda_bf16.h>
#include <cstdint>
#include <cstddef>

#define BB 4
#define HH 160
#define WW 160
#define HWSZ (HH*WW)
#define CPAD 40          // padded channel stride (u16) for conv staging
#define FPAD 72          // padded k stride (u16) for fc/fusion phase
#define XPXS 33          // u32 stride per pixel in transpose smem
#define OPAD 132         // fp32 px stride in conv64fc output staging

typedef unsigned long long ull;

// ---------------- bf16 mma.sync helpers ------------------------------------
__device__ __forceinline__ void mma_bf16(float d[4], const uint32_t a[4],
                                         uint32_t b0, uint32_t b1) {
    asm volatile(
        "mma.sync.aligned.m16n8k16.row.col.f32.bf16.bf16.f32 "
        "{%0,%1,%2,%3}, {%4,%5,%6,%7}, {%8,%9}, {%0,%1,%2,%3};"
        : "+f"(d[0]), "+f"(d[1]), "+f"(d[2]), "+f"(d[3])
        : "r"(a[0]), "r"(a[1]), "r"(a[2]), "r"(a[3]), "r"(b0), "r"(b1));
}
__device__ __forceinline__ uint32_t bfpack2(float x, float y) {
    __nv_bfloat162 h = __halves2bfloat162(__float2bfloat16(x), __float2bfloat16(y));
    return *(uint32_t*)&h;
}
__device__ __forceinline__ float bfunp_lo(uint32_t v) {
    __nv_bfloat162 h = *(__nv_bfloat162*)&v;
    return __bfloat162float(__low2bfloat16(h));
}
__device__ __forceinline__ float bfunp_hi(uint32_t v) {
    __nv_bfloat162 h = *(__nv_bfloat162*)&v;
    return __bfloat162float(__high2bfloat16(h));
}
__device__ __forceinline__ uint32_t packbf(float v0, float v1, uint32_t& lo) {
    __nv_bfloat16 h0 = __float2bfloat16(v0);
    __nv_bfloat16 h1 = __float2bfloat16(v1);
    lo = bfpack2(v0 - __bfloat162float(h0), v1 - __bfloat162float(h1));
    return (uint32_t)(*(uint16_t*)&h0) | ((uint32_t)(*(uint16_t*)&h1) << 16);
}

// ---------------- scratch (device globals; no allocation allowed) ----------
__device__ __align__(128) float g_gmap[BB*HWSZ];
__device__ __align__(128) float g_smap[BB*HWSZ];
__device__ __align__(128) float g_Weff[64*64];
__device__ __align__(128) float g_beff[64];
__device__ __align__(128) float g_b2[64];
__device__ __align__(128) uint4 g_wf[9216];       // conv64 frags
__device__ __align__(128) uint4 g_fcf[1024];      // fc frags
__device__ __align__(128) uint4 g_wf1[4608];      // conv32 frags
__device__ __align__(128) uint4 g_wff[1024];      // Weff (fusion) frags
__device__ __align__(128) uint16_t g_xh[(size_t)BB*HWSZ*64];  // x bf16 hi, ch-last
__device__ __align__(128) uint16_t g_xl[(size_t)BB*HWSZ*64];  // x bf16 lo
__device__ __align__(128) uint16_t g_fh[(size_t)BB*HWSZ*64];  // fusion hi, ch-last
__device__ __align__(128) uint16_t g_fl[(size_t)BB*HWSZ*64];  // fusion lo

// ---------------- K0a: effective dyn1d weights (sum over K) ----------------
__global__ void build_weff(const float* __restrict__ rk5w, const float* __restrict__ rk5b,
                           const float* __restrict__ rk7w, const float* __restrict__ rk7b,
                           const float* __restrict__ lk5w, const float* __restrict__ lk5b,
                           const float* __restrict__ lk7w, const float* __restrict__ lk7b)
{
    int id = blockIdx.x*blockDim.x + threadIdx.x;
    if (id >= 64*64) return;
    int m = id >> 6, c = id & 63;
    const float* w; const float* bs; int K, o;
    if      (m < 16) { w = rk5w; bs = rk5b; K = 5; o = m;    }
    else if (m < 32) { w = rk7w; bs = rk7b; K = 7; o = m-16; }
    else if (m < 48) { w = lk5w; bs = lk5b; K = 5; o = m-32; }
    else             { w = lk7w; bs = lk7b; K = 7; o = m-48; }
    float acc = 0.f;
    for (int k = 0; k < K; k++) acc += w[(o*K + k)*64 + c];
    g_Weff[m*64 + c] = acc;
    if (c == 0) {
        float bacc = 0.f;
        for (int k = 0; k < K; k++) bacc += bs[o*K + k];
        g_beff[m] = bacc;
    }
}

// ---------------- K0b: all remaining weight prep (after build_weff) --------
// id ranges: [0,9216) conv64 frags | [9216,10240) fc frags |
//            [10240,14848) conv32 frags | [14848,15872) Weff frags |
//            [15872,15936) BN-folded bias
__global__ void prep_all(const float* __restrict__ sfw, const float* __restrict__ bg,
                         const float* __restrict__ bv, const float* __restrict__ fcw,
                         const float* __restrict__ w1,
                         const float* __restrict__ b2s, const float* __restrict__ bbta,
                         const float* __restrict__ bm)
{
    int id = blockIdx.x*blockDim.x + threadIdx.x;
    if (id < 9216) {
        int lane = id & 31; int rem = id >> 5;
        int nt = rem & 7; rem >>= 3;
        int ks = rem & 1; rem >>= 1;
        int kh = rem & 1; int t = rem >> 1;
        int n  = nt*8 + (lane >> 2);
        int k0 = kh*32 + ks*16 + (lane & 3)*2;
        float sc = bg[n] * rsqrtf(bv[n] + 1e-5f);
        float w00 = sfw[(n*64 + k0    )*9 + t] * sc;
        float w01 = sfw[(n*64 + k0 + 1)*9 + t] * sc;
        float w08 = sfw[(n*64 + k0 + 8)*9 + t] * sc;
        float w09 = sfw[(n*64 + k0 + 9)*9 + t] * sc;
        uint4 rec;
        rec.x = packbf(w00, w01, rec.z);
        rec.y = packbf(w08, w09, rec.w);
        g_wf[id] = rec;
    } else if (id < 10240) {
        int fid = id - 9216;
        int lane = fid & 31; int rem = fid >> 5;
        int nt = rem & 7; int ks = rem >> 3;
        int n  = nt*8 + (lane >> 2);
        int k0 = ks*16 + (lane & 3)*2;
        uint4 rec;
        rec.x = packbf(fcw[n*64 + k0    ], fcw[n*64 + k0 + 1], rec.z);
        rec.y = packbf(fcw[n*64 + k0 + 8], fcw[n*64 + k0 + 9], rec.w);
        g_fcf[fid] = rec;
    } else if (id < 14848) {
        int fid = id - 10240;
        int lane = fid & 31; int rem = fid >> 5;
        int nt = rem & 3; rem >>= 2;
        int ks = rem & 1; rem >>= 1;
        int kh = rem & 1; int t = rem >> 1;
        int n  = nt*8 + (lane >> 2);
        int k0 = kh*32 + ks*16 + (lane & 3)*2;
        uint4 rec;
        rec.x = packbf(w1[(n*64 + k0    )*9 + t], w1[(n*64 + k0 + 1)*9 + t], rec.z);
        rec.y = packbf(w1[(n*64 + k0 + 8)*9 + t], w1[(n*64 + k0 + 9)*9 + t], rec.w);
        g_wf1[fid] = rec;
    } else if (id < 15872) {
        int fid = id - 14848;
        int lane = fid & 31; int rem = fid >> 5;
        int nt = rem & 7; int ks = rem >> 3;
        int n  = nt*8 + (lane >> 2);
        int k0 = ks*16 + (lane & 3)*2;
        uint4 rec;
        rec.x = packbf(g_Weff[n*64 + k0    ], g_Weff[n*64 + k0 + 1], rec.z);
        rec.y = packbf(g_Weff[n*64 + k0 + 8], g_Weff[n*64 + k0 + 9], rec.w);
        g_wff[fid] = rec;
    } else if (id < 15936) {
        int c = id - 15872;
        float scc = bg[c] * rsqrtf(bv[c] + 1e-5f);
        g_b2[c] = b2s[c]*scc + bbta[c] - bm[c]*scc;
    }
}

// ---------------- K0d: transpose x -> channel-last bf16 hi/lo --------------
__global__ __launch_bounds__(256)
void xpose_k(const float* __restrict__ x)
{
    __shared__ uint32_t s_h[128*XPXS];
    __shared__ uint32_t s_l[128*XPXS];
    const int tid = threadIdx.x;
    const int b   = blockIdx.y;
    const int px0 = blockIdx.x*128;
    const int px  = tid & 127;
    const int hf  = tid >> 7;

    #pragma unroll
    for (int c2 = 0; c2 < 16; c2++) {
        int c = hf*32 + c2*2;
        const float* fp = x + ((size_t)(b*64 + c))*HWSZ + px0 + px;
        float v0 = fp[0];
        float v1 = fp[HWSZ];
        uint32_t lw;
        uint32_t hw = packbf(v0, v1, lw);
        s_h[px*XPXS + hf*16 + c2] = hw;
        s_l[px*XPXS + hf*16 + c2] = lw;
    }
    __syncthreads();

    uint32_t* xh32 = (uint32_t*)g_xh;
    uint32_t* xl32 = (uint32_t*)g_xl;
    #pragma unroll
    for (int k = 0; k < 4; k++) {
        int idx = tid + k*256;
        int p = idx >> 3, q = idx & 7;
        size_t ga = ((size_t)b*HWSZ + px0 + p)*32 + q*4;
        uint4 hv, lv;
        hv.x = s_h[p*XPXS + q*4    ]; hv.y = s_h[p*XPXS + q*4 + 1];
        hv.z = s_h[p*XPXS + q*4 + 2]; hv.w = s_h[p*XPXS + q*4 + 3];
        lv.x = s_l[p*XPXS + q*4    ]; lv.y = s_l[p*XPXS + q*4 + 1];
        lv.z = s_l[p*XPXS + q*4 + 2]; lv.w = s_l[p*XPXS + q*4 + 3];
        *(uint4*)&xh32[ga] = hv;
        *(uint4*)&xl32[ga] = lv;
    }
}

// ---------------- K1: conv3x3<32> + sobel edge + attention via mma.sync ----
__global__ __launch_bounds__(256)
void conv32_edge_mma(const uint4* __restrict__ wf1, const float* __restrict__ b1,
                     const float* __restrict__ baw2, const float* __restrict__ bab2)
{
    __shared__ __align__(16) uint16_t s_hi[204*CPAD];
    __shared__ __align__(16) uint16_t s_lo[204*CPAD];
    __shared__ float s_ep[2][128], s_sp[2][128];
    __shared__ float s_b1[32], s_w2[32];

    const int tid = threadIdx.x;
    const int wid = tid >> 5, lane = tid & 31;
    const int g = lane >> 2, t2 = (lane & 3) * 2;
    const int b  = blockIdx.z;
    const int w0 = blockIdx.x*32, h0 = blockIdx.y*4;

    if (tid < 32) { s_b1[tid] = b1[tid]; s_w2[tid] = baw2[tid]; }

    const int m0 = wid*16 + g, m1 = m0 + 8;
    const int ph0 = m0 >> 5, pw0 = m0 & 31;
    const int ph1 = m1 >> 5, pw1 = m1 & 31;

    const int ep  = tid & 127;
    const int cig = tid >> 7;
    const int eph = ep >> 5, epw = ep & 31;

    const uint32_t* xh32 = (const uint32_t*)g_xh + (size_t)b*HWSZ*32;
    const uint32_t* xl32 = (const uint32_t*)g_xl + (size_t)b*HWSZ*32;

    float d[4][4];
    #pragma unroll
    for (int nt = 0; nt < 4; nt++)
        #pragma unroll
        for (int i = 0; i < 4; i++) d[nt][i] = 0.f;
    float edge_acc = 0.f, sum_acc = 0.f;

    for (int kh = 0; kh < 2; kh++) {
        if (kh) __syncthreads();
        #pragma unroll
        for (int it = 0; it < 4; it++) {
            int idx = tid + it*256;
            if (idx < 816) {
                int pos = idx >> 2, q = idx & 3;
                int h = pos/34, w = pos%34;
                int gh = h0 - 1 + h, gw = w0 - 1 + w;
                bool inb = (gh >= 0 && gh < HH && gw >= 0 && gw < WW);
                uint4 hv = make_uint4(0,0,0,0), lv = make_uint4(0,0,0,0);
                if (inb) {
                    size_t ga = ((size_t)(gh*WW + gw))*32 + kh*16 + q*4;
                    hv = *(const uint4*)&xh32[ga];
                    lv = *(const uint4*)&xl32[ga];
                }
                *(uint4*)&s_hi[pos*CPAD + q*8] = hv;
                *(uint4*)&s_lo[pos*CPAD + q*8] = lv;
            }
        }
        __syncthreads();

        // ---- edge (hi-only) + channel-sum (hi+lo) partials ----
        {
            float v[7][16];
            const int base_h = eph, base_w = epw;
            #pragma unroll
            for (int ppos = 0; ppos < 7; ppos++) {
                int dh, dw;
                if (ppos < 6) {
                    if (kh == 0) { dh = ppos >> 1; dw = (ppos & 1) * 2; }
                    else         { dh = (ppos & 1) * 2; dw = ppos >> 1; }
                } else { dh = 1; dw = 1; }
                int hw = (base_h + dh)*34 + (base_w + dw);
                const uint4* ph_ = (const uint4*)&s_hi[hw*CPAD + cig*16];
                #pragma unroll
                for (int q = 0; q < 2; q++) {
                    uint4 hv = ph_[q];
                    const uint32_t hw_[4] = {hv.x, hv.y, hv.z, hv.w};
                    #pragma unroll
                    for (int r = 0; r < 4; r++) {
                        v[ppos][q*8 + r*2    ] = bfunp_lo(hw_[r]);
                        v[ppos][q*8 + r*2 + 1] = bfunp_hi(hw_[r]);
                    }
                }
                if (ppos == 6) {
                    const uint4* pl_ = (const uint4*)&s_lo[hw*CPAD + cig*16];
                    #pragma unroll
                    for (int q = 0; q < 2; q++) {
                        uint4 lv = pl_[q];
                        const uint32_t lw_[4] = {lv.x, lv.y, lv.z, lv.w};
                        #pragma unroll
                        for (int r = 0; r < 4; r++) {
                            v[6][q*8 + r*2    ] += bfunp_lo(lw_[r]);
                            v[6][q*8 + r*2 + 1] += bfunp_hi(lw_[r]);
                        }
                    }
                }
            }
            float e = 0.f, s = 0.f;
            #pragma unroll
            for (int c = 0; c < 16; c++) {
                s += v[6][c];
                float gsum = (v[1][c] - v[0][c]) + 2.f*(v[3][c] - v[2][c]) + (v[5][c] - v[4][c]);
                e += fabsf(gsum);
            }
            edge_acc += e;
            sum_acc  += s;
        }

        // ---- conv MMAs: (ah+al)*bh ----
        for (int t = 0; t < 9; t++) {
            const int dr = t/3, dc = t%3;
            const int r0 = ((ph0 + dr)*34 + pw0 + dc)*CPAD;
            const int r1 = ((ph1 + dr)*34 + pw1 + dc)*CPAD;
            #pragma unroll
            for (int ks = 0; ks < 2; ks++) {
                uint2 bfr[4];
                const uint2* wp = (const uint2*)(wf1 + (size_t)(((t*2 + kh)*2 + ks)*4)*32 + lane);
                #pragma unroll
                for (int nt = 0; nt < 4; nt++) bfr[nt] = wp[nt*64];

                const int k = ks*16 + t2;
                uint32_t ah[4], al[4];
                ah[0] = *(const uint32_t*)&s_hi[r0 + k];
                ah[1] = *(const uint32_t*)&s_hi[r1 + k];
                ah[2] = *(const uint32_t*)&s_hi[r0 + k + 8];
                ah[3] = *(const uint32_t*)&s_hi[r1 + k + 8];
                al[0] = *(const uint32_t*)&s_lo[r0 + k];
                al[1] = *(const uint32_t*)&s_lo[r1 + k];
                al[2] = *(const uint32_t*)&s_lo[r0 + k + 8];
                al[3] = *(const uint32_t*)&s_lo[r1 + k + 8];

                #pragma unroll
                for (int nt = 0; nt < 4; nt++) {
                    mma_bf16(d[nt], ah, bfr[nt].x, bfr[nt].y);
                    mma_bf16(d[nt], al, bfr[nt].x, bfr[nt].y);
                }
            }
        }
    }

    s_ep[cig][ep] = edge_acc;
    s_sp[cig][ep] = sum_acc;

    float att0 = 0.f, att1 = 0.f;
    #pragma unroll
    for (int nt = 0; nt < 4; nt++) {
        int oc = nt*8 + t2;
        float b0v = s_b1[oc], b1v = s_b1[oc+1];
        float w0v = s_w2[oc], w1v = s_w2[oc+1];
        att0 += w0v*fmaxf(d[nt][0] + b0v, 0.f) + w1v*fmaxf(d[nt][1] + b1v, 0.f);
        att1 += w0v*fmaxf(d[nt][2] + b0v, 0.f) + w1v*fmaxf(d[nt][3] + b1v, 0.f);
    }
    att0 += __shfl_xor_sync(0xFFFFFFFF, att0, 1);
    att0 += __shfl_xor_sync(0xFFFFFFFF, att0, 2);
    att1 += __shfl_xor_sync(0xFFFFFFFF, att1, 1);
    att1 += __shfl_xor_sync(0xFFFFFFFF, att1, 2);
    __syncthreads();

    if ((lane & 3) == 0) {
        float bb = bab2[0];
        #pragma unroll
        for (int r = 0; r < 2; r++) {
            int m = r ? m1 : m0;
            float att = (r ? att1 : att0) + bb;
            float ed = (s_ep[0][m] + s_ep[1][m]) * (1.f/32.f);
            float sx =  s_sp[0][m] + s_sp[1][m];
            float z = att + ed;
            float a = 1.f / (1.f + expf(-z));
            float gv = 1.f + a;
            int mh = m >> 5, mw = m & 31;
            size_t pix = (size_t)b*HWSZ + (size_t)(h0 + mh)*WW + (w0 + mw);
            g_gmap[pix] = gv;
            g_smap[pix] = gv * sx;
        }
    }
}

// ---------------- K3: fusion GEMM via bf16 mma.sync ------------------------
__global__ __launch_bounds__(256)
void fusion_mma()
{
    __shared__ __align__(16) uint16_t s_buf[2*128*FPAD];
    __shared__ float s_be[64];

    const int tid = threadIdx.x;
    const int wid = tid >> 5, lane = tid & 31;
    const int g = lane >> 2, t2 = (lane & 3) * 2;
    const int b   = blockIdx.y;
    const int px0 = blockIdx.x*128;

    if (tid < 64) s_be[tid] = g_beff[tid];

    uint16_t* s_hi = s_buf;
    uint16_t* s_lo = s_buf + 128*FPAD;

    const uint32_t* xh32 = (const uint32_t*)g_xh + ((size_t)b*HWSZ + px0)*32;
    const uint32_t* xl32 = (const uint32_t*)g_xl + ((size_t)b*HWSZ + px0)*32;

    #pragma unroll
    for (int it = 0; it < 4; it++) {
        int idx = tid + it*256;
        int p = idx >> 3, q = idx & 7;
        uint4 hv = *(const uint4*)&xh32[(size_t)p*32 + q*4];
        uint4 lv = *(const uint4*)&xl32[(size_t)p*32 + q*4];
        *(uint4*)&s_hi[p*FPAD + q*8] = hv;
        *(uint4*)&s_lo[p*FPAD + q*8] = lv;
    }
    __syncthreads();

    const int m0 = wid*16 + g, m1 = m0 + 8;

    float d[8][4];
    #pragma unroll
    for (int nt = 0; nt < 8; nt++)
        #pragma unroll
        for (int i = 0; i < 4; i++) d[nt][i] = 0.f;

    #pragma unroll
    for (int ks = 0; ks < 4; ks++) {
        uint4 bfr[8];
        const uint4* wp = g_wff + (ks*8)*32 + lane;
        #pragma unroll
        for (int nt = 0; nt < 8; nt++) bfr[nt] = wp[nt*32];

        const int k = ks*16 + t2;
        uint32_t ah[4], al[4];
        ah[0] = *(const uint32_t*)&s_hi[m0*FPAD + k];
        ah[1] = *(const uint32_t*)&s_hi[m1*FPAD + k];
        ah[2] = *(const uint32_t*)&s_hi[m0*FPAD + k + 8];
        ah[3] = *(const uint32_t*)&s_hi[m1*FPAD + k + 8];
        al[0] = *(const uint32_t*)&s_lo[m0*FPAD + k];
        al[1] = *(const uint32_t*)&s_lo[m1*FPAD + k];
        al[2] = *(const uint32_t*)&s_lo[m0*FPAD + k + 8];
        al[3] = *(const uint32_t*)&s_lo[m1*FPAD + k + 8];

        #pragma unroll
        for (int nt = 0; nt < 8; nt++) {
            mma_bf16(d[nt], ah, bfr[nt].x, bfr[nt].y);
            mma_bf16(d[nt], al, bfr[nt].x, bfr[nt].y);
            mma_bf16(d[nt], ah, bfr[nt].z, bfr[nt].w);
        }
    }

    const float g0 = g_gmap[(size_t)b*HWSZ + px0 + m0];
    const float s0 = g_smap[(size_t)b*HWSZ + px0 + m0];
    const float g1 = g_gmap[(size_t)b*HWSZ + px0 + m1];
    const float s1 = g_smap[(size_t)b*HWSZ + px0 + m1];

    uint32_t* fh32 = (uint32_t*)g_fh + ((size_t)b*HWSZ + px0)*32;
    uint32_t* fl32 = (uint32_t*)g_fl + ((size_t)b*HWSZ + px0)*32;
    #pragma unroll
    for (int nt = 0; nt < 8; nt++) {
        int ch = nt*8 + t2;
        float be0 = s_be[ch], be1 = s_be[ch+1];
        uint32_t l0, l1;
        uint32_t h0v = packbf(s0*(g0*d[nt][0] + be0), s0*(g0*d[nt][1] + be1), l0);
        uint32_t h1v = packbf(s1*(g1*d[nt][2] + be0), s1*(g1*d[nt][3] + be1), l1);
        fh32[(size_t)m0*32 + (ch >> 1)] = h0v;
        fl32[(size_t)m0*32 + (ch >> 1)] = l0;
        fh32[(size_t)m1*32 + (ch >> 1)] = h1v;
        fl32[(size_t)m1*32 + (ch >> 1)] = l1;
    }
}

// ---------------- K4: conv3x3<64> + fc + residual via bf16 mma.sync --------
// Coalesced epilogue: D -> smem fp32 [64][OPAD], then warp-per-(ch,row)
// coalesced resid add + out store.
__global__ __launch_bounds__(256)
void conv64fc_mma(const uint4* __restrict__ wf, const float* __restrict__ b2,
                  const uint4* __restrict__ fcf, const float* __restrict__ fcb,
                  const float* __restrict__ resid, float* __restrict__ out)
{
    __shared__ __align__(16) uint16_t s_buf[2*128*FPAD];   // 36864B; reused as fp32 [64][OPAD]
    __shared__ float s_b2[64], s_fcb[64];

    const int tid = threadIdx.x;
    const int wid = tid >> 5, lane = tid & 31;
    const int g = lane >> 2, t2 = (lane & 3) * 2;
    const int b  = blockIdx.z;
    const int w0 = blockIdx.x*32, h0 = blockIdx.y*4;

    if (tid < 64) { s_b2[tid] = b2[tid]; s_fcb[tid] = fcb[tid]; }

    uint16_t* s_hi = s_buf;
    uint16_t* s_lo = s_buf + 128*FPAD;

    const uint32_t* fh32 = (const uint32_t*)g_fh + (size_t)b*HWSZ*32;
    const uint32_t* fl32 = (const uint32_t*)g_fl + (size_t)b*HWSZ*32;

    const int m0 = wid*16 + g, m1 = m0 + 8;
    const int ph0 = m0 >> 5, pw0 = m0 & 31;
    const int ph1 = m1 >> 5, pw1 = m1 & 31;

    float d[8][4];
    #pragma unroll
    for (int nt = 0; nt < 8; nt++)
        #pragma unroll
        for (int i = 0; i < 4; i++) d[nt][i] = 0.f;

    for (int kh = 0; kh < 2; kh++) {
        if (kh) __syncthreads();
        #pragma unroll
        for (int it = 0; it < 4; it++) {
            int idx = tid + it*256;
            if (idx < 816) {
                int pos = idx >> 2, q = idx & 3;
                int h = pos/34, w = pos%34;
                int gh = h0 - 1 + h, gw = w0 - 1 + w;
                bool inb = (gh >= 0 && gh < HH && gw >= 0 && gw < WW);
                uint4 hv = make_uint4(0,0,0,0), lv = make_uint4(0,0,0,0);
                if (inb) {
                    size_t ga = ((size_t)(gh*WW + gw))*32 + kh*16 + q*4;
                    hv = *(const uint4*)&fh32[ga];
                    lv = *(const uint4*)&fl32[ga];
                }
                *(uint4*)&s_hi[pos*CPAD + q*8] = hv;
                *(uint4*)&s_lo[pos*CPAD + q*8] = lv;
            }
        }
        __syncthreads();

        for (int t = 0; t < 9; t++) {
            const int dr = t/3, dc = t%3;
            const int r0 = ((ph0 + dr)*34 + pw0 + dc)*CPAD;
            const int r1 = ((ph1 + dr)*34 + pw1 + dc)*CPAD;
            #pragma unroll
            for (int ks = 0; ks < 2; ks++) {
                uint4 bfr[8];
                const uint4* wp = wf + (size_t)(((t*2 + kh)*2 + ks)*8)*32 + lane;
                #pragma unroll
                for (int nt = 0; nt < 8; nt++) bfr[nt] = wp[nt*32];

                const int k = ks*16 + t2;
                uint32_t ah[4], al[4];
                ah[0] = *(const uint32_t*)&s_hi[r0 + k];
                ah[1] = *(const uint32_t*)&s_hi[r1 + k];
                ah[2] = *(const uint32_t*)&s_hi[r0 + k + 8];
                ah[3] = *(const uint32_t*)&s_hi[r1 + k + 8];
                al[0] = *(const uint32_t*)&s_lo[r0 + k];
                al[1] = *(const uint32_t*)&s_lo[r1 + k];
                al[2] = *(const uint32_t*)&s_lo[r0 + k + 8];
                al[3] = *(const uint32_t*)&s_lo[r1 + k + 8];

                #pragma unroll
                for (int nt = 0; nt < 8; nt++) {
                    mma_bf16(d[nt], ah, bfr[nt].x, bfr[nt].y);
                    mma_bf16(d[nt], al, bfr[nt].x, bfr[nt].y);
                    mma_bf16(d[nt], ah, bfr[nt].z, bfr[nt].w);
                }
            }
        }
    }
    __syncthreads();

    uint16_t* f_hi = s_buf;
    uint16_t* f_lo = s_buf + 128*FPAD;
    #pragma unroll
    for (int nt = 0; nt < 8; nt++) {
        int oc = nt*8 + t2;
        float b0v = s_b2[oc], b1v = s_b2[oc+1];
        float v00 = fmaxf(d[nt][0] + b0v, 0.f);
        float v01 = fmaxf(d[nt][1] + b1v, 0.f);
        float v10 = fmaxf(d[nt][2] + b0v, 0.f);
        float v11 = fmaxf(d[nt][3] + b1v, 0.f);
        uint32_t l0, l1;
        uint32_t h0v = packbf(v00, v01, l0);
        uint32_t h1v = packbf(v10, v11, l1);
        *(uint32_t*)&f_hi[m0*FPAD + oc] = h0v;
        *(uint32_t*)&f_hi[m1*FPAD + oc] = h1v;
        *(uint32_t*)&f_lo[m0*FPAD + oc] = l0;
        *(uint32_t*)&f_lo[m1*FPAD + oc] = l1;
    }
    __syncthreads();

    float e[8][4];
    #pragma unroll
    for (int nt = 0; nt < 8; nt++)
        #pragma unroll
        for (int i = 0; i < 4; i++) e[nt][i] = 0.f;

    #pragma unroll
    for (int ks = 0; ks < 4; ks++) {
        uint4 bfr[8];
        const uint4* wp = fcf + (ks*8)*32 + lane;
        #pragma unroll
        for (int nt = 0; nt < 8; nt++) bfr[nt] = wp[nt*32];

        const int k = ks*16 + t2;
        uint32_t ah[4], al[4];
        ah[0] = *(const uint32_t*)&f_hi[m0*FPAD + k];
        ah[1] = *(const uint32_t*)&f_hi[m1*FPAD + k];
        ah[2] = *(const uint32_t*)&f_hi[m0*FPAD + k + 8];
        ah[3] = *(const uint32_t*)&f_hi[m1*FPAD + k + 8];
        al[0] = *(const uint32_t*)&f_lo[m0*FPAD + k];
        al[1] = *(const uint32_t*)&f_lo[m1*FPAD + k];
        al[2] = *(const uint32_t*)&f_lo[m0*FPAD + k + 8];
        al[3] = *(const uint32_t*)&f_lo[m1*FPAD + k + 8];

        #pragma unroll
        for (int nt = 0; nt < 8; nt++) {
            mma_bf16(e[nt], ah, bfr[nt].x, bfr[nt].y);
            mma_bf16(e[nt], al, bfr[nt].x, bfr[nt].y);
            mma_bf16(e[nt], ah, bfr[nt].z, bfr[nt].w);
        }
    }
    __syncthreads();   // f_hi/f_lo reads done; reuse s_buf as fp32 staging

    // stage fc result into smem [64 ch][OPAD px] (bank-conflict free)
    float* s_o = (float*)s_buf;      // 64*OPAD*4 = 33792B <= 36864B
    #pragma unroll
    for (int nt = 0; nt < 8; nt++) {
        int oc = nt*8 + t2;
        s_o[ oc   *OPAD + m0] = e[nt][0];
        s_o[(oc+1)*OPAD + m0] = e[nt][1];
        s_o[ oc   *OPAD + m1] = e[nt][2];
        s_o[(oc+1)*OPAD + m1] = e[nt][3];
    }
    __syncthreads();

    // coalesced write-out: warp-per-(ch,row), 32 consecutive px per store
    const size_t base = (size_t)b*64*HWSZ + (size_t)h0*WW + w0;
    #pragma unroll
    for (int it = 0; it < 32; it++) {
        int task = wid*32 + it;          // 0..255
        int ch = task >> 2, row = task & 3;
        float v = s_o[ch*OPAD + row*32 + lane] + s_fcb[ch];
        size_t idx = base + (size_t)ch*HWSZ + row*WW + lane;
        out[idx] = v + resid[idx];
    }
}

// ---------------------------------------------------------------------------
extern "C" void kernel_launch(void* const* d_in, const int* in_sizes, int n_in,
                              void* d_out, int out_size)
{
    (void)in_sizes; (void)n_in; (void)out_size;
    const float* x     = (const float*)d_in[0];
    const float* ba_w1 = (const float*)d_in[1];
    const float* ba_b1 = (const float*)d_in[2];
    const float* ba_w2 = (const float*)d_in[3];
    const float* ba_b2 = (const float*)d_in[4];
    // d_in[5..12]: offset branch — dead code in the reference, skipped.
    const float* rk5w  = (const float*)d_in[13];
    const float* rk5b  = (const float*)d_in[14];
    const float* rk7w  = (const float*)d_in[15];
    const float* rk7b  = (const float*)d_in[16];
    const float* lk5w  = (const float*)d_in[17];
    const float* lk5b  = (const float*)d_in[18];
    const float* lk7w  = (const float*)d_in[19];
    const float* lk7b  = (const float*)d_in[20];
    const float* sfw   = (const float*)d_in[21];
    const float* sfb   = (const float*)d_in[22];
    const float* sfg   = (const float*)d_in[23];
    const float* sfbb  = (const float*)d_in[24];
    const float* sfm   = (const float*)d_in[25];
    const float* sfv   = (const float*)d_in[26];
    const float* fcw   = (const float*)d_in[27];
    const float* fcb   = (const float*)d_in[28];
    float* out = (float*)d_out;

    float *pB2;
    uint4 *pWf, *pFcf, *pWf1;
    cudaGetSymbolAddress((void**)&pB2,   g_b2);
    cudaGetSymbolAddress((void**)&pWf,   g_wf);
    cudaGetSymbolAddress((void**)&pFcf,  g_fcf);
    cudaGetSymbolAddress((void**)&pWf1,  g_wf1);

    build_weff<<<16, 256>>>(rk5w, rk5b, rk7w, rk7b, lk5w, lk5b, lk7w, lk7b);
    prep_all<<<63, 256>>>(sfw, sfg, sfv, fcw, ba_w1, sfb, sfbb, sfm);
    xpose_k<<<dim3(HWSZ/128, BB), 256>>>(x);

    conv32_edge_mma<<<dim3(WW/32, HH/4, BB), 256>>>(pWf1, ba_b1, ba_w2, ba_b2);
    fusion_mma<<<dim3(HWSZ/128, BB), 256>>>();
    conv64fc_mma<<<dim3(WW/32, HH/4, BB), 256>>>(pWf, pB2, pFcf, fcb, x, out);
}